// round 1
// baseline (speedup 1.0000x reference)
#include <cuda_runtime.h>
#include <math.h>
#include <stdint.h>

#define Bsz   4096
#define Isz   1024
#define Hsz   1024
#define AHsz  128
#define FOURH 4096
#define FOURAH 512
#define THW   1152           // H + AH
#define LN_EPS 1e-5f

#define OFF_H ((size_t)Bsz * Hsz)                     // start of new_total_h in out
#define OFF_C (OFF_H + (size_t)Bsz * THW)             // start of new_total_c in out
#define OUT_FULL_SIZE (OFF_C + (size_t)Bsz * THW)     // 13,631,488

// ---------------- scratch (__device__ globals; no allocations allowed) ---------------
__device__ float g_igpre[(size_t)Bsz * FOURAH];   // 8 MB
__device__ float g_hgpre[(size_t)Bsz * FOURAH];   // 8 MB
__device__ float g_zw[(size_t)Bsz * 128];         // 2 MB
__device__ float g_zb[(size_t)Bsz * 128];         // 2 MB
__device__ float g_ing[(size_t)Bsz * FOURH];      // 64 MB
__device__ float g_hidg[(size_t)Bsz * FOURH];     // 64 MB

// ---------------- helpers ----------------
__device__ __forceinline__ float sigf(float x) { return 1.f / (1.f + expf(-x)); }

// Block-wide sum, result broadcast to all threads. nwarp = blockDim.x/32.
__device__ __forceinline__ float blockSum(float v, float* red, int t, int nwarp) {
    #pragma unroll
    for (int o = 16; o > 0; o >>= 1) v += __shfl_xor_sync(0xffffffffu, v, o);
    __syncthreads();
    if ((t & 31) == 0) red[t >> 5] = v;
    __syncthreads();
    float s = 0.f;
    for (int w = 0; w < nwarp; w++) s += red[w];
    return s;
}

// ---------------- generic SIMT fp32 GEMM ----------------
// C[M x N] = A[M x K] * Bw[N x K]^T  (both row-major; C row-major)
// SPLIT_A: A columns [0,splitK) come from A0 (lda0), [splitK,K) from A1 (lda1).
// EPI: in-place transform acc -> acc*alpha + bias + beta where
//      alpha[m,n] = sum_p zw[m, s*16+p] * alphaW[s, n%1024, p],  s = sOffset + n/1024
//      beta [m,n] = sum_p zb[m, s*16+p] * betaW [s, n%1024, p]
template<bool SPLIT_A, bool EPI>
__global__ __launch_bounds__(256)
void gemm_kernel(const float* __restrict__ A0, int lda0,
                 const float* __restrict__ A1, int lda1, int splitK,
                 const float* __restrict__ Bw,
                 float* __restrict__ C, int N, int K,
                 const float* __restrict__ alphaW,
                 const float* __restrict__ betaW,
                 const float* __restrict__ zw,
                 const float* __restrict__ zb,
                 const float* __restrict__ bias,
                 int sOffset)
{
    __shared__ float As[8][128];
    __shared__ float Bs[8][128];

    const int t  = threadIdx.x;
    const int m0 = blockIdx.y * 128;
    const int n0 = blockIdx.x * 128;
    const int loadRow = t >> 1;
    const int loadCol = (t & 1) * 4;
    const int tx = t & 15;
    const int ty = t >> 4;

    float acc[8][8];
    #pragma unroll
    for (int i = 0; i < 8; i++)
        #pragma unroll
        for (int j = 0; j < 8; j++) acc[i][j] = 0.f;

    for (int k0 = 0; k0 < K; k0 += 8) {
        const float* Ap = A0; int lda = lda0; int kk = k0;
        if (SPLIT_A) {
            if (k0 >= splitK) { Ap = A1; lda = lda1; kk = k0 - splitK; }
        }
        float4 av = *(const float4*)(Ap + (size_t)(m0 + loadRow) * lda + kk + loadCol);
        float4 bv = *(const float4*)(Bw + (size_t)(n0 + loadRow) * K + k0 + loadCol);
        __syncthreads();
        As[loadCol + 0][loadRow] = av.x; As[loadCol + 1][loadRow] = av.y;
        As[loadCol + 2][loadRow] = av.z; As[loadCol + 3][loadRow] = av.w;
        Bs[loadCol + 0][loadRow] = bv.x; Bs[loadCol + 1][loadRow] = bv.y;
        Bs[loadCol + 2][loadRow] = bv.z; Bs[loadCol + 3][loadRow] = bv.w;
        __syncthreads();
        #pragma unroll
        for (int k = 0; k < 8; k++) {
            float ar[8], br[8];
            *(float4*)(ar)     = *(const float4*)(&As[k][ty * 8]);
            *(float4*)(ar + 4) = *(const float4*)(&As[k][ty * 8 + 4]);
            *(float4*)(br)     = *(const float4*)(&Bs[k][tx * 8]);
            *(float4*)(br + 4) = *(const float4*)(&Bs[k][tx * 8 + 4]);
            #pragma unroll
            for (int i = 0; i < 8; i++)
                #pragma unroll
                for (int j = 0; j < 8; j++)
                    acc[i][j] += ar[i] * br[j];
        }
    }

    if (EPI) {
        __shared__ float aW[128][17];
        __shared__ float bW[128][17];
        __shared__ float zwS[128][16];
        __shared__ float zbS[128][16];
        const int s = sOffset + (n0 >> 10);
        const int hbase = n0 & 1023;
        const float* aSrc = alphaW + ((size_t)s * 1024 + hbase) * 16;
        const float* bSrc = betaW  + ((size_t)s * 1024 + hbase) * 16;
        for (int idx = t; idx < 2048; idx += 256) {
            int r = idx >> 4, p = idx & 15;
            aW[r][p] = aSrc[idx];
            bW[r][p] = bSrc[idx];
        }
        for (int idx = t; idx < 512; idx += 256) {
            int r = idx >> 2, q = (idx & 3) * 4;
            float4 zv  = *(const float4*)(zw + (size_t)(m0 + r) * 128 + s * 16 + q);
            float4 zbv = *(const float4*)(zb + (size_t)(m0 + r) * 128 + s * 16 + q);
            zwS[r][q] = zv.x;  zwS[r][q + 1] = zv.y;  zwS[r][q + 2] = zv.z;  zwS[r][q + 3] = zv.w;
            zbS[r][q] = zbv.x; zbS[r][q + 1] = zbv.y; zbS[r][q + 2] = zbv.z; zbS[r][q + 3] = zbv.w;
        }
        __syncthreads();
        #pragma unroll
        for (int j = 0; j < 8; j++) {
            const int gn = tx * 8 + j;
            float aWr[16], bWr[16];
            #pragma unroll
            for (int p = 0; p < 16; p++) { aWr[p] = aW[gn][p]; bWr[p] = bW[gn][p]; }
            const float bb = bias[n0 + gn];
            #pragma unroll
            for (int i = 0; i < 8; i++) {
                const int gm = ty * 8 + i;
                float al = 0.f, be = 0.f;
                #pragma unroll
                for (int p = 0; p < 16; p++) { al += zwS[gm][p] * aWr[p]; be += zbS[gm][p] * bWr[p]; }
                acc[i][j] = acc[i][j] * al + bb + be;
            }
        }
    }

    #pragma unroll
    for (int i = 0; i < 8; i++) {
        float4 v0 = make_float4(acc[i][0], acc[i][1], acc[i][2], acc[i][3]);
        float4 v1 = make_float4(acc[i][4], acc[i][5], acc[i][6], acc[i][7]);
        float* cp = C + (size_t)(m0 + ty * 8 + i) * N + n0 + tx * 8;
        *(float4*)cp       = v0;
        *(float4*)(cp + 4) = v1;
    }
}

// ---------------- adapter pointwise: LN(512)x2, gates, LN(128), ada, zw/zb ----------------
__global__ __launch_bounds__(128)
void adapter_pointwise(const float* __restrict__ igpre, const float* __restrict__ hgpre,
                       const float* __restrict__ total_c,
                       const float* __restrict__ a_ln_i_w, const float* __restrict__ a_ln_i_b,
                       const float* __restrict__ a_ln_h_w, const float* __restrict__ a_ln_h_b,
                       const float* __restrict__ a_ln_c_w, const float* __restrict__ a_ln_c_b,
                       const float* __restrict__ norm_zw_w, const float* __restrict__ norm_zw_b,
                       const float* __restrict__ bias_zb_w,
                       float* __restrict__ zw_out, float* __restrict__ zb_out,
                       float* __restrict__ out, int writeFull)
{
    __shared__ float sg[512];
    __shared__ float sh[512];
    __shared__ float sada[128];
    __shared__ float red[4];
    const int b = blockIdx.x;
    const int t = threadIdx.x;

    for (int i = t; i < 512; i += 128) {
        sg[i] = igpre[(size_t)b * 512 + i];
        sh[i] = hgpre[(size_t)b * 512 + i];
    }
    __syncthreads();

    float v1 = 0.f, v2 = 0.f;
    for (int i = t; i < 512; i += 128) { v1 += sg[i]; v2 += sh[i]; }
    float muI = blockSum(v1, red, t, 4) * (1.f / 512.f);
    float muH = blockSum(v2, red, t, 4) * (1.f / 512.f);
    v1 = 0.f; v2 = 0.f;
    for (int i = t; i < 512; i += 128) {
        float d = sg[i] - muI; v1 += d * d;
        d = sh[i] - muH; v2 += d * d;
    }
    float rsI = rsqrtf(blockSum(v1, red, t, 4) * (1.f / 512.f) + LN_EPS);
    float rsH = rsqrtf(blockSum(v2, red, t, 4) * (1.f / 512.f) + LN_EPS);
    __syncthreads();

    for (int i = t; i < 512; i += 128) {
        float g = (sg[i] - muI) * rsI * a_ln_i_w[i] + a_ln_i_b[i]
                + (sh[i] - muH) * rsH * a_ln_h_w[i] + a_ln_h_b[i];
        sg[i] = g;
    }
    __syncthreads();

    // gi, gf, gj, go order for the adapter
    float ac   = total_c[(size_t)b * THW + 1024 + t];
    float cpre = sigf(sg[128 + t]) * ac + sigf(sg[t]) * tanhf(sg[256 + t]);
    float mc = blockSum(cpre, red, t, 4) * (1.f / 128.f);
    float dc = cpre - mc;
    float vc = blockSum(dc * dc, red, t, 4) * (1.f / 128.f);
    float acy = dc * rsqrtf(vc + LN_EPS) * a_ln_c_w[t] + a_ln_c_b[t];
    float ada = sigf(sg[384 + t]) * tanhf(acy);
    sada[t] = ada;
    if (writeFull) {
        out[OFF_H + (size_t)b * THW + 1024 + t] = ada;
        out[OFF_C + (size_t)b * THW + 1024 + t] = acy;
    }
    __syncthreads();

    // zw[b,s,i] = ada . norm_zw_w[s,i,:] + norm_zw_b[s,i] ; zb similar (no bias)
    const float* wz = norm_zw_w + (size_t)t * 128;
    const float* wb = bias_zb_w + (size_t)t * 128;
    float az = 0.f, ab = 0.f;
    #pragma unroll 4
    for (int a = 0; a < 128; a++) { float av = sada[a]; az += av * wz[a]; ab += av * wb[a]; }
    zw_out[(size_t)b * 128 + t] = az + norm_zw_b[t];
    zb_out[(size_t)b * 128 + t] = ab;
}

// ---------------- main pointwise: LN(4096)x2, gates, LN(1024), hy/cy ----------------
__global__ __launch_bounds__(256)
void main_pointwise(const float* __restrict__ ing, const float* __restrict__ hidg,
                    const float* __restrict__ total_c,
                    const float* __restrict__ ln_i_w, const float* __restrict__ ln_i_b,
                    const float* __restrict__ ln_h_w, const float* __restrict__ ln_h_b,
                    const float* __restrict__ ln_c_w, const float* __restrict__ ln_c_b,
                    float* __restrict__ out, int writeFull)
{
    __shared__ float sIn[4096];
    __shared__ float sHid[4096];
    __shared__ float red[8];
    const int b = blockIdx.x;
    const int t = threadIdx.x;

    const float4* pi = (const float4*)(ing  + (size_t)b * 4096);
    const float4* ph = (const float4*)(hidg + (size_t)b * 4096);
    for (int i = t; i < 1024; i += 256) {
        ((float4*)sIn)[i]  = pi[i];
        ((float4*)sHid)[i] = ph[i];
    }
    __syncthreads();

    float v1 = 0.f, v2 = 0.f;
    for (int i = t; i < 4096; i += 256) { v1 += sIn[i]; v2 += sHid[i]; }
    float muI = blockSum(v1, red, t, 8) * (1.f / 4096.f);
    float muH = blockSum(v2, red, t, 8) * (1.f / 4096.f);
    v1 = 0.f; v2 = 0.f;
    for (int i = t; i < 4096; i += 256) {
        float d = sIn[i] - muI; v1 += d * d;
        d = sHid[i] - muH; v2 += d * d;
    }
    float rsI = rsqrtf(blockSum(v1, red, t, 8) * (1.f / 4096.f) + LN_EPS);
    float rsH = rsqrtf(blockSum(v2, red, t, 8) * (1.f / 4096.f) + LN_EPS);
    __syncthreads();

    for (int m = t; m < 4096; m += 256) {
        float g = (sIn[m]  - muI) * rsI * ln_i_w[m] + ln_i_b[m]
                + (sHid[m] - muH) * rsH * ln_h_w[m] + ln_h_b[m];
        sIn[m] = g;
    }
    __syncthreads();

    // i, j, f, o order for the main cell
    for (int h = t; h < 1024; h += 256) {
        float gi = sIn[h], gj = sIn[1024 + h], gf = sIn[2048 + h], go = sIn[3072 + h];
        float cx = total_c[(size_t)b * THW + h];
        float cpre = sigf(gf) * cx + sigf(gi) * tanhf(gj);
        sHid[h] = cpre;
        sHid[1024 + h] = go;
    }
    __syncthreads();

    v1 = 0.f;
    for (int h = t; h < 1024; h += 256) v1 += sHid[h];
    float mc = blockSum(v1, red, t, 8) * (1.f / 1024.f);
    v1 = 0.f;
    for (int h = t; h < 1024; h += 256) { float d = sHid[h] - mc; v1 += d * d; }
    float rc = rsqrtf(blockSum(v1, red, t, 8) * (1.f / 1024.f) + LN_EPS);

    for (int h = t; h < 1024; h += 256) {
        float cy = (sHid[h] - mc) * rc * ln_c_w[h] + ln_c_b[h];
        float hy = sigf(sHid[1024 + h]) * tanhf(cy);
        out[(size_t)b * 1024 + h] = hy;
        if (writeFull) {
            out[OFF_H + (size_t)b * THW + h] = hy;
            out[OFF_C + (size_t)b * THW + h] = cy;
        }
    }
}

// ---------------- launch ----------------
extern "C" void kernel_launch(void* const* d_in, const int* in_sizes, int n_in,
                              void* d_out, int out_size)
{
    const float* x           = (const float*)d_in[0];
    const float* total_h     = (const float*)d_in[1];
    const float* total_c     = (const float*)d_in[2];
    const float* w_ih        = (const float*)d_in[3];
    const float* w_hh        = (const float*)d_in[4];
    const float* b_ih        = (const float*)d_in[5];
    const float* b_hh        = (const float*)d_in[6];
    const float* ln_i_w      = (const float*)d_in[7];
    const float* ln_i_b      = (const float*)d_in[8];
    const float* ln_h_w      = (const float*)d_in[9];
    const float* ln_h_b      = (const float*)d_in[10];
    const float* ln_c_w      = (const float*)d_in[11];
    const float* ln_c_b      = (const float*)d_in[12];
    const float* norm_zw_w   = (const float*)d_in[13];
    const float* norm_zw_b   = (const float*)d_in[14];
    const float* norm_alpha_w= (const float*)d_in[15];
    const float* bias_zb_w   = (const float*)d_in[16];
    const float* bias_beta_w = (const float*)d_in[17];
    const float* a_w_ih      = (const float*)d_in[18];
    const float* a_w_hh      = (const float*)d_in[19];
    const float* a_ln_i_w    = (const float*)d_in[20];
    const float* a_ln_i_b    = (const float*)d_in[21];
    const float* a_ln_h_w    = (const float*)d_in[22];
    const float* a_ln_h_b    = (const float*)d_in[23];
    const float* a_ln_c_w    = (const float*)d_in[24];
    const float* a_ln_c_b    = (const float*)d_in[25];
    float* out = (float*)d_out;

    const int writeFull = (size_t)out_size >= OUT_FULL_SIZE ? 1 : 0;

    float *igpre, *hgpre, *zw, *zb, *ing, *hidg;
    cudaGetSymbolAddress((void**)&igpre, g_igpre);
    cudaGetSymbolAddress((void**)&hgpre, g_hgpre);
    cudaGetSymbolAddress((void**)&zw,    g_zw);
    cudaGetSymbolAddress((void**)&zb,    g_zb);
    cudaGetSymbolAddress((void**)&ing,   g_ing);
    cudaGetSymbolAddress((void**)&hidg,  g_hidg);

    dim3 thr(256);

    // adapter input GEMM: [x | hx] (B x 2048) @ a_w_ih^T -> (B x 512)
    gemm_kernel<true, false><<<dim3(FOURAH / 128, Bsz / 128), thr>>>(
        x, Isz, total_h, THW, Isz,
        a_w_ih, igpre, FOURAH, Isz + Hsz,
        nullptr, nullptr, nullptr, nullptr, nullptr, 0);

    // adapter hidden GEMM: ah (B x 128) @ a_w_hh^T -> (B x 512)
    gemm_kernel<false, false><<<dim3(FOURAH / 128, Bsz / 128), thr>>>(
        total_h + Hsz, THW, nullptr, 0, 0,
        a_w_hh, hgpre, FOURAH, AHsz,
        nullptr, nullptr, nullptr, nullptr, nullptr, 0);

    // adapter pointwise -> ada/acy outputs + zw/zb
    adapter_pointwise<<<Bsz, 128>>>(
        igpre, hgpre, total_c,
        a_ln_i_w, a_ln_i_b, a_ln_h_w, a_ln_h_b, a_ln_c_w, a_ln_c_b,
        norm_zw_w, norm_zw_b, bias_zb_w,
        zw, zb, out, writeFull);

    // in_g = (x @ w_ih^T) * alpha[:, :4] + b_ih + beta[:, :4]
    gemm_kernel<false, true><<<dim3(FOURH / 128, Bsz / 128), thr>>>(
        x, Isz, nullptr, 0, 0,
        w_ih, ing, FOURH, Isz,
        norm_alpha_w, bias_beta_w, zw, zb, b_ih, 0);

    // hid_g = (hx @ w_hh^T) * alpha[:, 4:] + b_hh + beta[:, 4:]
    gemm_kernel<false, true><<<dim3(FOURH / 128, Bsz / 128), thr>>>(
        total_h, THW, nullptr, 0, 0,
        w_hh, hidg, FOURH, Hsz,
        norm_alpha_w, bias_beta_w, zw, zb, b_hh, 4);

    // main pointwise -> hy, new_total_h[:, :H], new_total_c[:, :H]
    main_pointwise<<<Bsz, 256>>>(
        ing, hidg, total_c,
        ln_i_w, ln_i_b, ln_h_w, ln_h_b, ln_c_w, ln_c_b,
        out, writeFull);
}

// round 3
// speedup vs baseline: 2.7864x; 2.7864x over previous
#include <cuda_runtime.h>
#include <cuda_bf16.h>
#include <math.h>
#include <stdint.h>

#define Bsz   4096
#define Isz   1024
#define Hsz   1024
#define FOURH 4096
#define FOURAH 512
#define THW   1152
#define LN_EPS 1e-5f

#define OFF_H ((size_t)Bsz * Hsz)
#define OFF_C (OFF_H + (size_t)Bsz * THW)
#define OUT_FULL_SIZE (OFF_C + (size_t)Bsz * THW)

// ---------------- scratch ----------------
__device__ __nv_bfloat16 g_xh_hi[(size_t)Bsz * 2048];
__device__ __nv_bfloat16 g_xh_lo[(size_t)Bsz * 2048];
__device__ __nv_bfloat16 g_wm_hi[(size_t)2 * 4096 * 1024];
__device__ __nv_bfloat16 g_wm_lo[(size_t)2 * 4096 * 1024];
__device__ __nv_bfloat16 g_awih_hi[(size_t)512 * 2048];
__device__ __nv_bfloat16 g_awih_lo[(size_t)512 * 2048];
__device__ __nv_bfloat16 g_ah_hi[(size_t)Bsz * 128];
__device__ __nv_bfloat16 g_ah_lo[(size_t)Bsz * 128];
__device__ __nv_bfloat16 g_awhh_hi[(size_t)512 * 128];
__device__ __nv_bfloat16 g_awhh_lo[(size_t)512 * 128];
__device__ float g_igpre[(size_t)Bsz * FOURAH];
__device__ float g_hgpre[(size_t)Bsz * FOURAH];
__device__ float g_zw[(size_t)Bsz * 128];
__device__ float g_zb[(size_t)Bsz * 128];
__device__ float g_gates[(size_t)2 * Bsz * FOURH];

// ---------------- PTX helpers (sm_80-era, legal on sm_103 base target) ----------------
__device__ __forceinline__ uint32_t smem_u32(const void* p) {
    uint32_t a;
    asm("{ .reg .u64 t; cvta.to.shared.u64 t, %1; cvt.u32.u64 %0, t; }" : "=r"(a) : "l"(p));
    return a;
}
__device__ __forceinline__ void cp_async16(uint32_t smaddr, const void* gaddr) {
    asm volatile("cp.async.cg.shared.global [%0], [%1], 16;" :: "r"(smaddr), "l"(gaddr) : "memory");
}
#define CP_COMMIT() asm volatile("cp.async.commit_group;" ::: "memory")
#define CP_WAIT(n)  asm volatile("cp.async.wait_group %0;" :: "n"(n) : "memory")

__device__ __forceinline__ void ldmat4(uint32_t* r, uint32_t addr) {
    asm volatile("ldmatrix.sync.aligned.m8n8.x4.shared.b16 {%0,%1,%2,%3}, [%4];"
        : "=r"(r[0]), "=r"(r[1]), "=r"(r[2]), "=r"(r[3]) : "r"(addr));
}
__device__ __forceinline__ void mma16816(float* c, const uint32_t* a, const uint32_t* b) {
    asm volatile("mma.sync.aligned.m16n8k16.row.col.f32.bf16.bf16.f32 "
        "{%0,%1,%2,%3}, {%4,%5,%6,%7}, {%8,%9}, {%0,%1,%2,%3};"
        : "+f"(c[0]), "+f"(c[1]), "+f"(c[2]), "+f"(c[3])
        : "r"(a[0]), "r"(a[1]), "r"(a[2]), "r"(a[3]), "r"(b[0]), "r"(b[1]));
}

// ---------------- fp32 -> bf16 hi/lo split ----------------
__global__ __launch_bounds__(256)
void split_k(const float* __restrict__ src, int srcLd,
             __nv_bfloat16* __restrict__ hi, __nv_bfloat16* __restrict__ lo,
             int dstLd, int w4, int total4)
{
    int idx = blockIdx.x * blockDim.x + threadIdx.x;
    if (idx >= total4) return;
    int r = idx / w4, c4 = idx - r * w4;
    float4 v = *(const float4*)(src + (size_t)r * srcLd + c4 * 4);
    size_t d = (size_t)r * dstLd + c4 * 4;
    __nv_bfloat16 h0 = __float2bfloat16(v.x), h1 = __float2bfloat16(v.y);
    __nv_bfloat16 h2 = __float2bfloat16(v.z), h3 = __float2bfloat16(v.w);
    hi[d] = h0; hi[d + 1] = h1; hi[d + 2] = h2; hi[d + 3] = h3;
    lo[d]     = __float2bfloat16(v.x - __bfloat162float(h0));
    lo[d + 1] = __float2bfloat16(v.y - __bfloat162float(h1));
    lo[d + 2] = __float2bfloat16(v.z - __bfloat162float(h2));
    lo[d + 3] = __float2bfloat16(v.w - __bfloat162float(h3));
}

// ---------------- HMMA bf16x3 GEMM, CTA tile 128x128, K-chunks of 64, 3-stage cp.async ----
// C[M x N] = A[M x K] * B[N x K]^T. EPI fuses acc*alpha + bias + beta (rank-16, also HMMA).
#define STG_BYTES 65536
#define SMEM_SZ   (3 * STG_BYTES)

template<bool EPI>
__global__ __launch_bounds__(256, 1)
void gemm_hmma(const __nv_bfloat16* __restrict__ Ahi, const __nv_bfloat16* __restrict__ Alo,
               int lda, int aZoff,
               const __nv_bfloat16* __restrict__ Bhi, const __nv_bfloat16* __restrict__ Blo,
               long bZ,
               float* __restrict__ C, int ldc, long cZ, int K,
               const float* __restrict__ alphaW, const float* __restrict__ betaW,
               const float* __restrict__ zw, const float* __restrict__ zb,
               const float* __restrict__ bias0, const float* __restrict__ bias1)
{
    extern __shared__ char smem[];
    const uint32_t sb = smem_u32(smem);

    const int tid  = threadIdx.x;
    const int lane = tid & 31;
    const int wid  = tid >> 5;
    const int wm   = wid >> 2;          // 0..1  -> 64 M rows
    const int wn   = wid & 3;           // 0..3  -> 32 N cols
    const int m0 = blockIdx.y * 128;
    const int n0 = blockIdx.x * 128;
    const int z  = blockIdx.z;

    Ahi += (size_t)z * aZoff;  Alo += (size_t)z * aZoff;
    Bhi += (size_t)z * bZ;     Blo += (size_t)z * bZ;
    C   += (size_t)z * cZ;

    float acc[4][4][4];
    #pragma unroll
    for (int i = 0; i < 4; i++)
        #pragma unroll
        for (int j = 0; j < 4; j++)
            #pragma unroll
            for (int q = 0; q < 4; q++) acc[i][j][q] = 0.f;

    const int nCh = K >> 6;
    const int ldRow = tid >> 3;          // 0..31 base row per iteration group
    const int ldSeg = tid & 7;           // 16B segment 0..7

    auto load_stage = [&](int chunk, int buf) {
        const uint32_t sbase = sb + buf * STG_BYTES;
        const int kcol = chunk * 64;
        #pragma unroll
        for (int it = 0; it < 4; ++it) {
            const int row = ldRow + it * 32;
            const uint32_t so = (row << 7) + ((ldSeg ^ (row & 7)) << 4);
            const size_t ga = (size_t)(m0 + row) * lda + kcol + ldSeg * 8;
            cp_async16(sbase + so,          Ahi + ga);
            cp_async16(sbase + 16384 + so,  Alo + ga);
            const size_t gb = (size_t)(n0 + row) * K + kcol + ldSeg * 8;
            cp_async16(sbase + 32768 + so,  Bhi + gb);
            cp_async16(sbase + 49152 + so,  Blo + gb);
        }
    };

    load_stage(0, 0); CP_COMMIT();
    if (nCh > 1) load_stage(1, 1);
    CP_COMMIT();

    for (int c = 0; c < nCh; ++c) {
        CP_WAIT(1);
        __syncthreads();
        if (c + 2 < nCh) load_stage(c + 2, (c + 2) % 3);
        CP_COMMIT();

        const int buf = c % 3;
        const uint32_t aHiB = sb + buf * STG_BYTES;
        const uint32_t aLoB = aHiB + 16384;
        const char* bHiP = smem + buf * STG_BYTES + 32768;
        const char* bLoP = bHiP + 16384;

        #pragma unroll
        for (int ks = 0; ks < 4; ++ks) {
            uint32_t ahi[4][4], alo[4][4];
            const int rA = wm * 64 + (lane & 15);
            const int segA = ks * 2 + (lane >> 4);
            #pragma unroll
            for (int mi = 0; mi < 4; ++mi) {
                const int row = rA + mi * 16;
                const uint32_t ad = (row << 7) + ((segA ^ (row & 7)) << 4);
                ldmat4(ahi[mi], aHiB + ad);
                ldmat4(alo[mi], aLoB + ad);
            }
            uint32_t bhi[4][2], blo[4][2];
            const int rB = wn * 32 + (lane >> 2);
            const int off = (lane & 3) * 4;
            #pragma unroll
            for (int ni = 0; ni < 4; ++ni) {
                const int row = rB + ni * 8;
                const int s0 = (ks * 2) ^ (row & 7);
                const int s1 = (ks * 2 + 1) ^ (row & 7);
                bhi[ni][0] = *(const uint32_t*)(bHiP + row * 128 + s0 * 16 + off);
                bhi[ni][1] = *(const uint32_t*)(bHiP + row * 128 + s1 * 16 + off);
                blo[ni][0] = *(const uint32_t*)(bLoP + row * 128 + s0 * 16 + off);
                blo[ni][1] = *(const uint32_t*)(bLoP + row * 128 + s1 * 16 + off);
            }
            #pragma unroll
            for (int mi = 0; mi < 4; ++mi)
                #pragma unroll
                for (int ni = 0; ni < 4; ++ni) {
                    mma16816(acc[mi][ni], ahi[mi], bhi[ni]);
                    mma16816(acc[mi][ni], ahi[mi], blo[ni]);
                    mma16816(acc[mi][ni], alo[mi], bhi[ni]);
                }
        }
    }

    CP_WAIT(0);
    __syncthreads();

    if (EPI) {
        // reuse stage-0 smem for epilogue tables (bf16 hi/lo, rows padded to 48B)
        __nv_bfloat16* zwHi = (__nv_bfloat16*)(smem);
        __nv_bfloat16* zwLo = (__nv_bfloat16*)(smem + 6144);
        __nv_bfloat16* zbHi = (__nv_bfloat16*)(smem + 12288);
        __nv_bfloat16* zbLo = (__nv_bfloat16*)(smem + 18432);
        __nv_bfloat16* aWHi = (__nv_bfloat16*)(smem + 24576);
        __nv_bfloat16* aWLo = (__nv_bfloat16*)(smem + 30720);
        __nv_bfloat16* bWHi = (__nv_bfloat16*)(smem + 36864);
        __nv_bfloat16* bWLo = (__nv_bfloat16*)(smem + 43008);
        float* biasS = (float*)(smem + 49152);

        const int s = 4 * z + (n0 >> 10);
        const int hbase = n0 & 1023;
        for (int i = tid; i < 2048; i += 256) {
            const int r = i >> 4, p = i & 15;
            float v = zw[(size_t)(m0 + r) * 128 + s * 16 + p];
            __nv_bfloat16 h = __float2bfloat16(v);
            zwHi[r * 24 + p] = h; zwLo[r * 24 + p] = __float2bfloat16(v - __bfloat162float(h));
            v = zb[(size_t)(m0 + r) * 128 + s * 16 + p];
            h = __float2bfloat16(v);
            zbHi[r * 24 + p] = h; zbLo[r * 24 + p] = __float2bfloat16(v - __bfloat162float(h));
            v = alphaW[((size_t)s * 1024 + hbase + r) * 16 + p];
            h = __float2bfloat16(v);
            aWHi[r * 24 + p] = h; aWLo[r * 24 + p] = __float2bfloat16(v - __bfloat162float(h));
            v = betaW[((size_t)s * 1024 + hbase + r) * 16 + p];
            h = __float2bfloat16(v);
            bWHi[r * 24 + p] = h; bWLo[r * 24 + p] = __float2bfloat16(v - __bfloat162float(h));
        }
        if (tid < 128) biasS[tid] = (z ? bias1 : bias0)[n0 + tid];
        __syncthreads();

        // fragments
        const int rA = wm * 64 + (lane & 15);
        const uint32_t segOff = (lane >> 4) * 16;
        const int nB = wn * 32 + (lane >> 2);
        const int offB = (lane & 3) * 4;

        float eacc[4][4][4];

        // ---- alpha = zw @ aW^T (bf16x3), then acc *= alpha ----
        {
            uint32_t fAh[4][4], fAl[4][4];
            #pragma unroll
            for (int mi = 0; mi < 4; ++mi) {
                const int row = rA + mi * 16;
                ldmat4(fAh[mi], sb + 0    + row * 48 + segOff);
                ldmat4(fAl[mi], sb + 6144 + row * 48 + segOff);
            }
            #pragma unroll
            for (int mi = 0; mi < 4; ++mi)
                #pragma unroll
                for (int ni = 0; ni < 4; ++ni)
                    #pragma unroll
                    for (int q = 0; q < 4; ++q) eacc[mi][ni][q] = 0.f;
            #pragma unroll
            for (int ni = 0; ni < 4; ++ni) {
                const int row = nB + ni * 8;
                uint32_t bh[2], bl[2];
                bh[0] = *(const uint32_t*)((const char*)aWHi + row * 48 + offB);
                bh[1] = *(const uint32_t*)((const char*)aWHi + row * 48 + offB + 16);
                bl[0] = *(const uint32_t*)((const char*)aWLo + row * 48 + offB);
                bl[1] = *(const uint32_t*)((const char*)aWLo + row * 48 + offB + 16);
                #pragma unroll
                for (int mi = 0; mi < 4; ++mi) {
                    mma16816(eacc[mi][ni], fAh[mi], bh);
                    mma16816(eacc[mi][ni], fAh[mi], bl);
                    mma16816(eacc[mi][ni], fAl[mi], bh);
                }
            }
            #pragma unroll
            for (int mi = 0; mi < 4; ++mi)
                #pragma unroll
                for (int ni = 0; ni < 4; ++ni)
                    #pragma unroll
                    for (int q = 0; q < 4; ++q) acc[mi][ni][q] *= eacc[mi][ni][q];
        }

        // ---- beta = zb @ bW^T (bf16x3), acc += beta ----
        {
            uint32_t fAh[4][4], fAl[4][4];
            #pragma unroll
            for (int mi = 0; mi < 4; ++mi) {
                const int row = rA + mi * 16;
                ldmat4(fAh[mi], sb + 12288 + row * 48 + segOff);
                ldmat4(fAl[mi], sb + 18432 + row * 48 + segOff);
            }
            #pragma unroll
            for (int mi = 0; mi < 4; ++mi)
                #pragma unroll
                for (int ni = 0; ni < 4; ++ni)
                    #pragma unroll
                    for (int q = 0; q < 4; ++q) eacc[mi][ni][q] = 0.f;
            #pragma unroll
            for (int ni = 0; ni < 4; ++ni) {
                const int row = nB + ni * 8;
                uint32_t bh[2], bl[2];
                bh[0] = *(const uint32_t*)((const char*)bWHi + row * 48 + offB);
                bh[1] = *(const uint32_t*)((const char*)bWHi + row * 48 + offB + 16);
                bl[0] = *(const uint32_t*)((const char*)bWLo + row * 48 + offB);
                bl[1] = *(const uint32_t*)((const char*)bWLo + row * 48 + offB + 16);
                #pragma unroll
                for (int mi = 0; mi < 4; ++mi) {
                    mma16816(eacc[mi][ni], fAh[mi], bh);
                    mma16816(eacc[mi][ni], fAh[mi], bl);
                    mma16816(eacc[mi][ni], fAl[mi], bh);
                }
            }
            #pragma unroll
            for (int mi = 0; mi < 4; ++mi)
                #pragma unroll
                for (int ni = 0; ni < 4; ++ni)
                    #pragma unroll
                    for (int q = 0; q < 4; ++q) acc[mi][ni][q] += eacc[mi][ni][q];
        }

        // ---- + bias, store ----
        #pragma unroll
        for (int mi = 0; mi < 4; ++mi) {
            const int row = m0 + wm * 64 + mi * 16 + (lane >> 2);
            #pragma unroll
            for (int ni = 0; ni < 4; ++ni) {
                const int cl = wn * 32 + ni * 8 + (lane & 3) * 2;
                const float b0 = biasS[cl], b1 = biasS[cl + 1];
                float2 v0 = make_float2(acc[mi][ni][0] + b0, acc[mi][ni][1] + b1);
                float2 v1 = make_float2(acc[mi][ni][2] + b0, acc[mi][ni][3] + b1);
                *(float2*)(C + (size_t)row * ldc + n0 + cl)       = v0;
                *(float2*)(C + (size_t)(row + 8) * ldc + n0 + cl) = v1;
            }
        }
    } else {
        #pragma unroll
        for (int mi = 0; mi < 4; ++mi) {
            const int row = m0 + wm * 64 + mi * 16 + (lane >> 2);
            #pragma unroll
            for (int ni = 0; ni < 4; ++ni) {
                const int cl = wn * 32 + ni * 8 + (lane & 3) * 2;
                *(float2*)(C + (size_t)row * ldc + n0 + cl)       = make_float2(acc[mi][ni][0], acc[mi][ni][1]);
                *(float2*)(C + (size_t)(row + 8) * ldc + n0 + cl) = make_float2(acc[mi][ni][2], acc[mi][ni][3]);
            }
        }
    }
}

// ---------------- pointwise ----------------
__device__ __forceinline__ float sigf(float x) { return 1.f / (1.f + expf(-x)); }
__device__ __forceinline__ float blockSum(float v, float* red, int t, int nwarp) {
    #pragma unroll
    for (int o = 16; o > 0; o >>= 1) v += __shfl_xor_sync(0xffffffffu, v, o);
    __syncthreads();
    if ((t & 31) == 0) red[t >> 5] = v;
    __syncthreads();
    float s = 0.f;
    for (int w = 0; w < nwarp; w++) s += red[w];
    return s;
}

__global__ __launch_bounds__(128)
void adapter_pointwise(const float* __restrict__ igpre, const float* __restrict__ hgpre,
                       const float* __restrict__ total_c,
                       const float* __restrict__ a_ln_i_w, const float* __restrict__ a_ln_i_b,
                       const float* __restrict__ a_ln_h_w, const float* __restrict__ a_ln_h_b,
                       const float* __restrict__ a_ln_c_w, const float* __restrict__ a_ln_c_b,
                       const float* __restrict__ norm_zw_w, const float* __restrict__ norm_zw_b,
                       const float* __restrict__ bias_zb_w,
                       float* __restrict__ zw_out, float* __restrict__ zb_out,
                       float* __restrict__ out, int writeFull)
{
    __shared__ float sg[512];
    __shared__ float sh[512];
    __shared__ float sada[128];
    __shared__ float red[4];
    const int b = blockIdx.x;
    const int t = threadIdx.x;

    for (int i = t; i < 512; i += 128) {
        sg[i] = igpre[(size_t)b * 512 + i];
        sh[i] = hgpre[(size_t)b * 512 + i];
    }
    __syncthreads();

    float v1 = 0.f, v2 = 0.f;
    for (int i = t; i < 512; i += 128) { v1 += sg[i]; v2 += sh[i]; }
    float muI = blockSum(v1, red, t, 4) * (1.f / 512.f);
    float muH = blockSum(v2, red, t, 4) * (1.f / 512.f);
    v1 = 0.f; v2 = 0.f;
    for (int i = t; i < 512; i += 128) {
        float d = sg[i] - muI; v1 += d * d;
        d = sh[i] - muH; v2 += d * d;
    }
    float rsI = rsqrtf(blockSum(v1, red, t, 4) * (1.f / 512.f) + LN_EPS);
    float rsH = rsqrtf(blockSum(v2, red, t, 4) * (1.f / 512.f) + LN_EPS);
    __syncthreads();

    for (int i = t; i < 512; i += 128) {
        float g = (sg[i] - muI) * rsI * a_ln_i_w[i] + a_ln_i_b[i]
                + (sh[i] - muH) * rsH * a_ln_h_w[i] + a_ln_h_b[i];
        sg[i] = g;
    }
    __syncthreads();

    float ac   = total_c[(size_t)b * THW + 1024 + t];
    float cpre = sigf(sg[128 + t]) * ac + sigf(sg[t]) * tanhf(sg[256 + t]);
    float mc = blockSum(cpre, red, t, 4) * (1.f / 128.f);
    float dc = cpre - mc;
    float vc = blockSum(dc * dc, red, t, 4) * (1.f / 128.f);
    float acy = dc * rsqrtf(vc + LN_EPS) * a_ln_c_w[t] + a_ln_c_b[t];
    float ada = sigf(sg[384 + t]) * tanhf(acy);
    sada[t] = ada;
    if (writeFull) {
        out[OFF_H + (size_t)b * THW + 1024 + t] = ada;
        out[OFF_C + (size_t)b * THW + 1024 + t] = acy;
    }
    __syncthreads();

    const float* wz = norm_zw_w + (size_t)t * 128;
    const float* wb = bias_zb_w + (size_t)t * 128;
    float az = 0.f, ab = 0.f;
    #pragma unroll 4
    for (int a = 0; a < 128; a++) { float av = sada[a]; az += av * wz[a]; ab += av * wb[a]; }
    zw_out[(size_t)b * 128 + t] = az + norm_zw_b[t];
    zb_out[(size_t)b * 128 + t] = ab;
}

__global__ __launch_bounds__(256)
void main_pointwise(const float* __restrict__ ing, const float* __restrict__ hidg,
                    const float* __restrict__ total_c,
                    const float* __restrict__ ln_i_w, const float* __restrict__ ln_i_b,
                    const float* __restrict__ ln_h_w, const float* __restrict__ ln_h_b,
                    const float* __restrict__ ln_c_w, const float* __restrict__ ln_c_b,
                    float* __restrict__ out, int writeFull)
{
    __shared__ float sIn[4096];
    __shared__ float sHid[4096];
    __shared__ float red[8];
    const int b = blockIdx.x;
    const int t = threadIdx.x;

    const float4* pi = (const float4*)(ing  + (size_t)b * 4096);
    const float4* ph = (const float4*)(hidg + (size_t)b * 4096);
    for (int i = t; i < 1024; i += 256) {
        ((float4*)sIn)[i]  = pi[i];
        ((float4*)sHid)[i] = ph[i];
    }
    __syncthreads();

    float v1 = 0.f, v2 = 0.f;
    for (int i = t; i < 4096; i += 256) { v1 += sIn[i]; v2 += sHid[i]; }
    float muI = blockSum(v1, red, t, 8) * (1.f / 4096.f);
    float muH = blockSum(v2, red, t, 8) * (1.f / 4096.f);
    v1 = 0.f; v2 = 0.f;
    for (int i = t; i < 4096; i += 256) {
        float d = sIn[i] - muI; v1 += d * d;
        d = sHid[i] - muH; v2 += d * d;
    }
    float rsI = rsqrtf(blockSum(v1, red, t, 8) * (1.f / 4096.f) + LN_EPS);
    float rsH = rsqrtf(blockSum(v2, red, t, 8) * (1.f / 4096.f) + LN_EPS);
    __syncthreads();

    for (int mI = t; mI < 4096; mI += 256) {
        float g = (sIn[mI]  - muI) * rsI * ln_i_w[mI] + ln_i_b[mI]
                + (sHid[mI] - muH) * rsH * ln_h_w[mI] + ln_h_b[mI];
        sIn[mI] = g;
    }
    __syncthreads();

    for (int h = t; h < 1024; h += 256) {
        float gi = sIn[h], gj = sIn[1024 + h], gf = sIn[2048 + h], go = sIn[3072 + h];
        float cx = total_c[(size_t)b * THW + h];
        float cpre = sigf(gf) * cx + sigf(gi) * tanhf(gj);
        sHid[h] = cpre;
        sHid[1024 + h] = go;
    }
    __syncthreads();

    v1 = 0.f;
    for (int h = t; h < 1024; h += 256) v1 += sHid[h];
    float mc = blockSum(v1, red, t, 8) * (1.f / 1024.f);
    v1 = 0.f;
    for (int h = t; h < 1024; h += 256) { float d = sHid[h] - mc; v1 += d * d; }
    float rc = rsqrtf(blockSum(v1, red, t, 8) * (1.f / 1024.f) + LN_EPS);

    for (int h = t; h < 1024; h += 256) {
        float cy = (sHid[h] - mc) * rc * ln_c_w[h] + ln_c_b[h];
        float hy = sigf(sHid[1024 + h]) * tanhf(cy);
        out[(size_t)b * 1024 + h] = hy;
        if (writeFull) {
            out[OFF_H + (size_t)b * THW + h] = hy;
            out[OFF_C + (size_t)b * THW + h] = cy;
        }
    }
}

// ---------------- launch ----------------
extern "C" void kernel_launch(void* const* d_in, const int* in_sizes, int n_in,
                              void* d_out, int out_size)
{
    const float* x           = (const float*)d_in[0];
    const float* total_h     = (const float*)d_in[1];
    const float* total_c     = (const float*)d_in[2];
    const float* w_ih        = (const float*)d_in[3];
    const float* w_hh        = (const float*)d_in[4];
    const float* b_ih        = (const float*)d_in[5];
    const float* b_hh        = (const float*)d_in[6];
    const float* ln_i_w      = (const float*)d_in[7];
    const float* ln_i_b      = (const float*)d_in[8];
    const float* ln_h_w      = (const float*)d_in[9];
    const float* ln_h_b      = (const float*)d_in[10];
    const float* ln_c_w      = (const float*)d_in[11];
    const float* ln_c_b      = (const float*)d_in[12];
    const float* norm_zw_w   = (const float*)d_in[13];
    const float* norm_zw_b   = (const float*)d_in[14];
    const float* norm_alpha_w= (const float*)d_in[15];
    const float* bias_zb_w   = (const float*)d_in[16];
    const float* bias_beta_w = (const float*)d_in[17];
    const float* a_w_ih      = (const float*)d_in[18];
    const float* a_w_hh      = (const float*)d_in[19];
    const float* a_ln_i_w    = (const float*)d_in[20];
    const float* a_ln_i_b    = (const float*)d_in[21];
    const float* a_ln_h_w    = (const float*)d_in[22];
    const float* a_ln_h_b    = (const float*)d_in[23];
    const float* a_ln_c_w    = (const float*)d_in[24];
    const float* a_ln_c_b    = (const float*)d_in[25];
    float* out = (float*)d_out;

    const int writeFull = (size_t)out_size >= OUT_FULL_SIZE ? 1 : 0;

    __nv_bfloat16 *xh_hi, *xh_lo, *wm_hi, *wm_lo, *awih_hi, *awih_lo, *ah_hi, *ah_lo, *awhh_hi, *awhh_lo;
    float *igpre, *hgpre, *zw, *zb, *gates;
    cudaGetSymbolAddress((void**)&xh_hi, g_xh_hi);     cudaGetSymbolAddress((void**)&xh_lo, g_xh_lo);
    cudaGetSymbolAddress((void**)&wm_hi, g_wm_hi);     cudaGetSymbolAddress((void**)&wm_lo, g_wm_lo);
    cudaGetSymbolAddress((void**)&awih_hi, g_awih_hi); cudaGetSymbolAddress((void**)&awih_lo, g_awih_lo);
    cudaGetSymbolAddress((void**)&ah_hi, g_ah_hi);     cudaGetSymbolAddress((void**)&ah_lo, g_ah_lo);
    cudaGetSymbolAddress((void**)&awhh_hi, g_awhh_hi); cudaGetSymbolAddress((void**)&awhh_lo, g_awhh_lo);
    cudaGetSymbolAddress((void**)&igpre, g_igpre);     cudaGetSymbolAddress((void**)&hgpre, g_hgpre);
    cudaGetSymbolAddress((void**)&zw, g_zw);           cudaGetSymbolAddress((void**)&zb, g_zb);
    cudaGetSymbolAddress((void**)&gates, g_gates);

    cudaFuncSetAttribute(gemm_hmma<true>,  cudaFuncAttributeMaxDynamicSharedMemorySize, SMEM_SZ);
    cudaFuncSetAttribute(gemm_hmma<false>, cudaFuncAttributeMaxDynamicSharedMemorySize, SMEM_SZ);

    // ---- conversions ----
    {
        int t4 = Bsz * 1024 / 4;
        split_k<<<(t4 + 255) / 256, 256>>>(x, 1024, xh_hi, xh_lo, 2048, 256, t4);
        split_k<<<(t4 + 255) / 256, 256>>>(total_h, THW, xh_hi + 1024, xh_lo + 1024, 2048, 256, t4);
        int t4a = Bsz * 128 / 4;
        split_k<<<(t4a + 255) / 256, 256>>>(total_h + 1024, THW, ah_hi, ah_lo, 128, 32, t4a);
        int t4w = 4096 * 1024 / 4;
        split_k<<<(t4w + 255) / 256, 256>>>(w_ih, 1024, wm_hi, wm_lo, 1024, 256, t4w);
        split_k<<<(t4w + 255) / 256, 256>>>(w_hh, 1024, wm_hi + (size_t)4096 * 1024, wm_lo + (size_t)4096 * 1024, 1024, 256, t4w);
        int t4i = 512 * 2048 / 4;
        split_k<<<(t4i + 255) / 256, 256>>>(a_w_ih, 2048, awih_hi, awih_lo, 2048, 512, t4i);
        int t4h = 512 * 128 / 4;
        split_k<<<(t4h + 255) / 256, 256>>>(a_w_hh, 128, awhh_hi, awhh_lo, 128, 32, t4h);
    }

    // ---- adapter GEMMs ----
    gemm_hmma<false><<<dim3(4, 32, 1), 256, SMEM_SZ>>>(
        xh_hi, xh_lo, 2048, 0, awih_hi, awih_lo, 0,
        igpre, 512, 0, 2048,
        nullptr, nullptr, nullptr, nullptr, nullptr, nullptr);
    gemm_hmma<false><<<dim3(4, 32, 1), 256, SMEM_SZ>>>(
        ah_hi, ah_lo, 128, 0, awhh_hi, awhh_lo, 0,
        hgpre, 512, 0, 128,
        nullptr, nullptr, nullptr, nullptr, nullptr, nullptr);

    // ---- adapter pointwise ----
    adapter_pointwise<<<Bsz, 128>>>(
        igpre, hgpre, total_c,
        a_ln_i_w, a_ln_i_b, a_ln_h_w, a_ln_h_b, a_ln_c_w, a_ln_c_b,
        norm_zw_w, norm_zw_b, bias_zb_w,
        zw, zb, out, writeFull);

    // ---- main GEMMs (z=0: x@w_ih -> ing, z=1: hx@w_hh -> hidg), fused alpha/beta epilogue ----
    gemm_hmma<true><<<dim3(32, 32, 2), 256, SMEM_SZ>>>(
        xh_hi, xh_lo, 2048, 1024, wm_hi, wm_lo, (long)4096 * 1024,
        gates, 4096, (long)4096 * 4096, 1024,
        norm_alpha_w, bias_beta_w, zw, zb, b_ih, b_hh);

    // ---- main pointwise ----
    main_pointwise<<<Bsz, 256>>>(
        gates, gates + (size_t)4096 * 4096, total_c,
        ln_i_w, ln_i_b, ln_h_w, ln_h_b, ln_c_w, ln_c_b,
        out, writeFull);
}

// round 4
// speedup vs baseline: 2.9440x; 1.0566x over previous
#include <cuda_runtime.h>
#include <cuda_bf16.h>
#include <math.h>
#include <stdint.h>

#define Bsz   4096
#define FOURAH 512
#define THW   1152
#define LN_EPS 1e-5f

#define OFF_H ((size_t)Bsz * 1024)
#define OFF_C (OFF_H + (size_t)Bsz * THW)
#define OUT_FULL_SIZE (OFF_C + (size_t)Bsz * THW)

// ---------------- scratch ----------------
__device__ __nv_bfloat16 g_xh_hi[(size_t)Bsz * 2048];
__device__ __nv_bfloat16 g_xh_lo[(size_t)Bsz * 2048];
__device__ __nv_bfloat16 g_wm_hi[(size_t)2 * 4096 * 1024];
__device__ __nv_bfloat16 g_wm_lo[(size_t)2 * 4096 * 1024];
__device__ __nv_bfloat16 g_awih_hi[(size_t)512 * 2048];
__device__ __nv_bfloat16 g_awih_lo[(size_t)512 * 2048];
__device__ __nv_bfloat16 g_ah_hi[(size_t)Bsz * 128];
__device__ __nv_bfloat16 g_ah_lo[(size_t)Bsz * 128];
__device__ __nv_bfloat16 g_awhh_hi[(size_t)512 * 128];
__device__ __nv_bfloat16 g_awhh_lo[(size_t)512 * 128];
__device__ float g_igpre[(size_t)Bsz * FOURAH];
__device__ float g_hgpre[(size_t)Bsz * FOURAH];
__device__ float g_zw[(size_t)Bsz * 128];
__device__ float g_zb[(size_t)Bsz * 128];
__device__ float g_gates[(size_t)2 * Bsz * 4096];

// ---------------- PTX helpers ----------------
__device__ __forceinline__ uint32_t smem_u32(const void* p) {
    uint32_t a;
    asm("{ .reg .u64 t; cvta.to.shared.u64 t, %1; cvt.u32.u64 %0, t; }" : "=r"(a) : "l"(p));
    return a;
}
__device__ __forceinline__ void cp_async16(uint32_t smaddr, const void* gaddr) {
    asm volatile("cp.async.cg.shared.global [%0], [%1], 16;" :: "r"(smaddr), "l"(gaddr) : "memory");
}
#define CP_COMMIT() asm volatile("cp.async.commit_group;" ::: "memory")
#define CP_WAIT(n)  asm volatile("cp.async.wait_group %0;" :: "n"(n) : "memory")

__device__ __forceinline__ void ldmat4(uint32_t* r, uint32_t addr) {
    asm volatile("ldmatrix.sync.aligned.m8n8.x4.shared.b16 {%0,%1,%2,%3}, [%4];"
        : "=r"(r[0]), "=r"(r[1]), "=r"(r[2]), "=r"(r[3]) : "r"(addr));
}
__device__ __forceinline__ void mma16816(float* c, const uint32_t* a, const uint32_t* b) {
    asm volatile("mma.sync.aligned.m16n8k16.row.col.f32.bf16.bf16.f32 "
        "{%0,%1,%2,%3}, {%4,%5,%6,%7}, {%8,%9}, {%0,%1,%2,%3};"
        : "+f"(c[0]), "+f"(c[1]), "+f"(c[2]), "+f"(c[3])
        : "r"(a[0]), "r"(a[1]), "r"(a[2]), "r"(a[3]), "r"(b[0]), "r"(b[1]));
}

// ---------------- fp32 -> bf16 hi/lo split, 8 elems/thread, uint4 stores ----------------
struct SplitJob { const float* src; int srcLd; __nv_bfloat16* hi; __nv_bfloat16* lo; int dstLd; int w8; };

__device__ __forceinline__ void split8_do(const float* src, int srcLd,
                                          __nv_bfloat16* hi, __nv_bfloat16* lo,
                                          int dstLd, int w8, int idx)
{
    const int r = idx / w8, c = (idx - r * w8) * 8;
    const float* s = src + (size_t)r * srcLd + c;
    float4 v0 = *(const float4*)s;
    float4 v1 = *(const float4*)(s + 4);
    float f[8] = { v0.x, v0.y, v0.z, v0.w, v1.x, v1.y, v1.z, v1.w };
    __nv_bfloat16 h[8];
    __nv_bfloat16 l[8];
    #pragma unroll
    for (int i = 0; i < 8; ++i) {
        h[i] = __float2bfloat16(f[i]);
        l[i] = __float2bfloat16(f[i] - __bfloat162float(h[i]));
    }
    *(uint4*)(hi + (size_t)r * dstLd + c) = *(uint4*)h;
    *(uint4*)(lo + (size_t)r * dstLd + c) = *(uint4*)l;
}

__global__ __launch_bounds__(256)
void split_w(const float* __restrict__ w_ih, const float* __restrict__ w_hh,
             __nv_bfloat16* __restrict__ hi, __nv_bfloat16* __restrict__ lo)
{
    int idx = blockIdx.x * 256 + threadIdx.x;              // 524288 per z
    const float* src = blockIdx.z ? w_hh : w_ih;
    size_t off = (size_t)blockIdx.z * 4096 * 1024;
    split8_do(src, 1024, hi + off, lo + off, 1024, 128, idx);
}

__global__ __launch_bounds__(256)
void split_xh(const float* __restrict__ x, const float* __restrict__ total_h,
              __nv_bfloat16* __restrict__ hi, __nv_bfloat16* __restrict__ lo)
{
    int idx = blockIdx.x * 256 + threadIdx.x;              // 524288 per z
    if (blockIdx.z == 0) split8_do(x, 1024, hi, lo, 2048, 128, idx);
    else                 split8_do(total_h, THW, hi + 1024, lo + 1024, 2048, 128, idx);
}

__global__ __launch_bounds__(256)
void split_small(const float* __restrict__ total_h,
                 const float* __restrict__ a_w_ih, const float* __restrict__ a_w_hh,
                 __nv_bfloat16* __restrict__ ah_hi, __nv_bfloat16* __restrict__ ah_lo,
                 __nv_bfloat16* __restrict__ awih_hi, __nv_bfloat16* __restrict__ awih_lo,
                 __nv_bfloat16* __restrict__ awhh_hi, __nv_bfloat16* __restrict__ awhh_lo)
{
    int idx = blockIdx.x * 256 + threadIdx.x;
    if (idx < 65536)       split8_do(total_h + 1024, THW, ah_hi, ah_lo, 128, 16, idx);
    else if (idx < 196608) split8_do(a_w_ih, 2048, awih_hi, awih_lo, 2048, 256, idx - 65536);
    else if (idx < 204800) split8_do(a_w_hh, 128, awhh_hi, awhh_lo, 128, 16, idx - 196608);
}

// ---------------- HMMA bf16x3 GEMM, CTA tile 128x128, K-chunks of 64, 3-stage cp.async ----
#define STG_BYTES 65536
#define SMEM_SZ   (3 * STG_BYTES)

template<bool EPI, bool DUAL>
__global__ __launch_bounds__(256, 1)
void gemm_hmma(const __nv_bfloat16* __restrict__ Ahi_, const __nv_bfloat16* __restrict__ Alo_,
               int lda_, int aZoff,
               const __nv_bfloat16* __restrict__ Bhi_, const __nv_bfloat16* __restrict__ Blo_,
               long bZ,
               float* __restrict__ C_, int ldc_, long cZ, int K_,
               const __nv_bfloat16* __restrict__ A2hi, const __nv_bfloat16* __restrict__ A2lo,
               int lda2,
               const __nv_bfloat16* __restrict__ B2hi, const __nv_bfloat16* __restrict__ B2lo,
               float* __restrict__ C2, int ldc2, int K2,
               const float* __restrict__ alphaW, const float* __restrict__ betaW,
               const float* __restrict__ zw, const float* __restrict__ zb,
               const float* __restrict__ bias0, const float* __restrict__ bias1)
{
    extern __shared__ char smem[];
    const uint32_t sb = smem_u32(smem);

    const int tid  = threadIdx.x;
    const int lane = tid & 31;
    const int wid  = tid >> 5;
    const int wm   = wid >> 2;
    const int wn   = wid & 3;
    const int m0 = blockIdx.y * 128;
    const int n0 = blockIdx.x * 128;
    const int z  = blockIdx.z;

    const __nv_bfloat16 *Ahi, *Alo, *Bhi, *Blo;
    float* C;
    int lda, ldc, K;
    if (DUAL && z == 1) {
        Ahi = A2hi; Alo = A2lo; lda = lda2;
        Bhi = B2hi; Blo = B2lo;
        C = C2; ldc = ldc2; K = K2;
    } else {
        Ahi = Ahi_ + (size_t)z * aZoff; Alo = Alo_ + (size_t)z * aZoff; lda = lda_;
        Bhi = Bhi_ + (size_t)z * bZ;    Blo = Blo_ + (size_t)z * bZ;
        C = C_ + (size_t)z * cZ; ldc = ldc_; K = K_;
    }

    float acc[4][4][4];
    #pragma unroll
    for (int i = 0; i < 4; i++)
        #pragma unroll
        for (int j = 0; j < 4; j++)
            #pragma unroll
            for (int q = 0; q < 4; q++) acc[i][j][q] = 0.f;

    const int nCh = K >> 6;
    const int ldRow = tid >> 3;
    const int ldSeg = tid & 7;

    auto load_stage = [&](int chunk, int buf) {
        const uint32_t sbase = sb + buf * STG_BYTES;
        const int kcol = chunk * 64;
        #pragma unroll
        for (int it = 0; it < 4; ++it) {
            const int row = ldRow + it * 32;
            const uint32_t so = (row << 7) + ((ldSeg ^ (row & 7)) << 4);
            const size_t ga = (size_t)(m0 + row) * lda + kcol + ldSeg * 8;
            cp_async16(sbase + so,          Ahi + ga);
            cp_async16(sbase + 16384 + so,  Alo + ga);
            const size_t gb = (size_t)(n0 + row) * K + kcol + ldSeg * 8;
            cp_async16(sbase + 32768 + so,  Bhi + gb);
            cp_async16(sbase + 49152 + so,  Blo + gb);
        }
    };

    load_stage(0, 0); CP_COMMIT();
    if (nCh > 1) load_stage(1, 1);
    CP_COMMIT();

    for (int c = 0; c < nCh; ++c) {
        CP_WAIT(1);
        __syncthreads();
        if (c + 2 < nCh) load_stage(c + 2, (c + 2) % 3);
        CP_COMMIT();

        const int buf = c % 3;
        const uint32_t aHiB = sb + buf * STG_BYTES;
        const uint32_t aLoB = aHiB + 16384;
        const uint32_t bHiB = aHiB + 32768;
        const uint32_t bLoB = aHiB + 49152;

        #pragma unroll
        for (int ks = 0; ks < 4; ++ks) {
            // ---- A fragments via ldmatrix ----
            uint32_t ahi[4][4], alo[4][4];
            const int rA = wm * 64 + (lane & 15);
            const uint32_t sA = (uint32_t)(((ks * 2 + (lane >> 4)) ^ (rA & 7)) << 4);
            #pragma unroll
            for (int mi = 0; mi < 4; ++mi) {
                const uint32_t ad = (uint32_t)((rA + mi * 16) << 7) + sA;
                ldmat4(ahi[mi], aHiB + ad);
                ldmat4(alo[mi], aLoB + ad);
            }
            // ---- B fragments via ldmatrix (non-trans: [n][k] smem == mma B layout) ----
            uint32_t bhi[4][2], blo[4][2];
            #pragma unroll
            for (int p = 0; p < 2; ++p) {
                const int mi2 = lane >> 3;                       // matrix 0..3
                const int row = wn * 32 + (p * 2 + (mi2 >> 1)) * 8 + (lane & 7);
                const uint32_t seg = (uint32_t)(((ks * 2 + (mi2 & 1)) ^ (row & 7)) << 4);
                const uint32_t ad = (uint32_t)(row << 7) + seg;
                ldmat4(&bhi[p * 2][0], bHiB + ad);
                ldmat4(&blo[p * 2][0], bLoB + ad);
            }
            #pragma unroll
            for (int mi = 0; mi < 4; ++mi)
                #pragma unroll
                for (int ni = 0; ni < 4; ++ni) {
                    mma16816(acc[mi][ni], ahi[mi], bhi[ni]);
                    mma16816(acc[mi][ni], ahi[mi], blo[ni]);
                    mma16816(acc[mi][ni], alo[mi], bhi[ni]);
                }
        }
    }

    CP_WAIT(0);
    __syncthreads();

    if (EPI) {
        __nv_bfloat16* zwHi = (__nv_bfloat16*)(smem);
        __nv_bfloat16* zwLo = (__nv_bfloat16*)(smem + 6144);
        __nv_bfloat16* zbHi = (__nv_bfloat16*)(smem + 12288);
        __nv_bfloat16* zbLo = (__nv_bfloat16*)(smem + 18432);
        __nv_bfloat16* aWHi = (__nv_bfloat16*)(smem + 24576);
        __nv_bfloat16* aWLo = (__nv_bfloat16*)(smem + 30720);
        __nv_bfloat16* bWHi = (__nv_bfloat16*)(smem + 36864);
        __nv_bfloat16* bWLo = (__nv_bfloat16*)(smem + 43008);
        float* biasS = (float*)(smem + 49152);

        const int s = 4 * z + (n0 >> 10);
        const int hbase = n0 & 1023;
        for (int i = tid; i < 2048; i += 256) {
            const int r = i >> 4, p = i & 15;
            float v = zw[(size_t)(m0 + r) * 128 + s * 16 + p];
            __nv_bfloat16 h = __float2bfloat16(v);
            zwHi[r * 24 + p] = h; zwLo[r * 24 + p] = __float2bfloat16(v - __bfloat162float(h));
            v = zb[(size_t)(m0 + r) * 128 + s * 16 + p];
            h = __float2bfloat16(v);
            zbHi[r * 24 + p] = h; zbLo[r * 24 + p] = __float2bfloat16(v - __bfloat162float(h));
            v = alphaW[((size_t)s * 1024 + hbase + r) * 16 + p];
            h = __float2bfloat16(v);
            aWHi[r * 24 + p] = h; aWLo[r * 24 + p] = __float2bfloat16(v - __bfloat162float(h));
            v = betaW[((size_t)s * 1024 + hbase + r) * 16 + p];
            h = __float2bfloat16(v);
            bWHi[r * 24 + p] = h; bWLo[r * 24 + p] = __float2bfloat16(v - __bfloat162float(h));
        }
        if (tid < 128) biasS[tid] = (z ? bias1 : bias0)[n0 + tid];
        __syncthreads();

        const int rA = wm * 64 + (lane & 15);
        const uint32_t segOff = (lane >> 4) * 16;
        const int nB = wn * 32 + (lane >> 2);
        const int offB = (lane & 3) * 4;

        float eacc[4][4][4];

        // ---- alpha = zw @ aW^T (bf16x3), acc *= alpha ----
        {
            uint32_t fAh[4][4], fAl[4][4];
            #pragma unroll
            for (int mi = 0; mi < 4; ++mi) {
                const int row = rA + mi * 16;
                ldmat4(fAh[mi], sb + 0    + row * 48 + segOff);
                ldmat4(fAl[mi], sb + 6144 + row * 48 + segOff);
            }
            #pragma unroll
            for (int mi = 0; mi < 4; ++mi)
                #pragma unroll
                for (int ni = 0; ni < 4; ++ni)
                    #pragma unroll
                    for (int q = 0; q < 4; ++q) eacc[mi][ni][q] = 0.f;
            #pragma unroll
            for (int ni = 0; ni < 4; ++ni) {
                const int row = nB + ni * 8;
                uint32_t bh[2], bl[2];
                bh[0] = *(const uint32_t*)((const char*)aWHi + row * 48 + offB);
                bh[1] = *(const uint32_t*)((const char*)aWHi + row * 48 + offB + 16);
                bl[0] = *(const uint32_t*)((const char*)aWLo + row * 48 + offB);
                bl[1] = *(const uint32_t*)((const char*)aWLo + row * 48 + offB + 16);
                #pragma unroll
                for (int mi = 0; mi < 4; ++mi) {
                    mma16816(eacc[mi][ni], fAh[mi], bh);
                    mma16816(eacc[mi][ni], fAh[mi], bl);
                    mma16816(eacc[mi][ni], fAl[mi], bh);
                }
            }
            #pragma unroll
            for (int mi = 0; mi < 4; ++mi)
                #pragma unroll
                for (int ni = 0; ni < 4; ++ni)
                    #pragma unroll
                    for (int q = 0; q < 4; ++q) acc[mi][ni][q] *= eacc[mi][ni][q];
        }

        // ---- beta = zb @ bW^T (bf16x3), acc += beta ----
        {
            uint32_t fAh[4][4], fAl[4][4];
            #pragma unroll
            for (int mi = 0; mi < 4; ++mi) {
                const int row = rA + mi * 16;
                ldmat4(fAh[mi], sb + 12288 + row * 48 + segOff);
                ldmat4(fAl[mi], sb + 18432 + row * 48 + segOff);
            }
            #pragma unroll
            for (int mi = 0; mi < 4; ++mi)
                #pragma unroll
                for (int ni = 0; ni < 4; ++ni)
                    #pragma unroll
                    for (int q = 0; q < 4; ++q) eacc[mi][ni][q] = 0.f;
            #pragma unroll
            for (int ni = 0; ni < 4; ++ni) {
                const int row = nB + ni * 8;
                uint32_t bh[2], bl[2];
                bh[0] = *(const uint32_t*)((const char*)bWHi + row * 48 + offB);
                bh[1] = *(const uint32_t*)((const char*)bWHi + row * 48 + offB + 16);
                bl[0] = *(const uint32_t*)((const char*)bWLo + row * 48 + offB);
                bl[1] = *(const uint32_t*)((const char*)bWLo + row * 48 + offB + 16);
                #pragma unroll
                for (int mi = 0; mi < 4; ++mi) {
                    mma16816(eacc[mi][ni], fAh[mi], bh);
                    mma16816(eacc[mi][ni], fAh[mi], bl);
                    mma16816(eacc[mi][ni], fAl[mi], bh);
                }
            }
            #pragma unroll
            for (int mi = 0; mi < 4; ++mi)
                #pragma unroll
                for (int ni = 0; ni < 4; ++ni)
                    #pragma unroll
                    for (int q = 0; q < 4; ++q) acc[mi][ni][q] += eacc[mi][ni][q];
        }

        #pragma unroll
        for (int mi = 0; mi < 4; ++mi) {
            const int row = m0 + wm * 64 + mi * 16 + (lane >> 2);
            #pragma unroll
            for (int ni = 0; ni < 4; ++ni) {
                const int cl = wn * 32 + ni * 8 + (lane & 3) * 2;
                const float b0 = biasS[cl], b1 = biasS[cl + 1];
                *(float2*)(C + (size_t)row * ldc + n0 + cl)       = make_float2(acc[mi][ni][0] + b0, acc[mi][ni][1] + b1);
                *(float2*)(C + (size_t)(row + 8) * ldc + n0 + cl) = make_float2(acc[mi][ni][2] + b0, acc[mi][ni][3] + b1);
            }
        }
    } else {
        #pragma unroll
        for (int mi = 0; mi < 4; ++mi) {
            const int row = m0 + wm * 64 + mi * 16 + (lane >> 2);
            #pragma unroll
            for (int ni = 0; ni < 4; ++ni) {
                const int cl = wn * 32 + ni * 8 + (lane & 3) * 2;
                *(float2*)(C + (size_t)row * ldc + n0 + cl)       = make_float2(acc[mi][ni][0], acc[mi][ni][1]);
                *(float2*)(C + (size_t)(row + 8) * ldc + n0 + cl) = make_float2(acc[mi][ni][2], acc[mi][ni][3]);
            }
        }
    }
}

// ---------------- pointwise ----------------
__device__ __forceinline__ float sigf(float x) { return 1.f / (1.f + expf(-x)); }
__device__ __forceinline__ float blockSum(float v, float* red, int t, int nwarp) {
    #pragma unroll
    for (int o = 16; o > 0; o >>= 1) v += __shfl_xor_sync(0xffffffffu, v, o);
    __syncthreads();
    if ((t & 31) == 0) red[t >> 5] = v;
    __syncthreads();
    float s = 0.f;
    for (int w = 0; w < nwarp; w++) s += red[w];
    return s;
}

__global__ __launch_bounds__(128)
void adapter_pointwise(const float* __restrict__ igpre, const float* __restrict__ hgpre,
                       const float* __restrict__ total_c,
                       const float* __restrict__ a_ln_i_w, const float* __restrict__ a_ln_i_b,
                       const float* __restrict__ a_ln_h_w, const float* __restrict__ a_ln_h_b,
                       const float* __restrict__ a_ln_c_w, const float* __restrict__ a_ln_c_b,
                       const float* __restrict__ norm_zw_w, const float* __restrict__ norm_zw_b,
                       const float* __restrict__ bias_zb_w,
                       float* __restrict__ zw_out, float* __restrict__ zb_out,
                       float* __restrict__ out, int writeFull)
{
    __shared__ float sg[512];
    __shared__ float sh[512];
    __shared__ float sada[128];
    __shared__ float red[4];
    const int b = blockIdx.x;
    const int t = threadIdx.x;

    for (int i = t; i < 512; i += 128) {
        sg[i] = igpre[(size_t)b * 512 + i];
        sh[i] = hgpre[(size_t)b * 512 + i];
    }
    __syncthreads();

    float v1 = 0.f, v2 = 0.f;
    for (int i = t; i < 512; i += 128) { v1 += sg[i]; v2 += sh[i]; }
    float muI = blockSum(v1, red, t, 4) * (1.f / 512.f);
    float muH = blockSum(v2, red, t, 4) * (1.f / 512.f);
    v1 = 0.f; v2 = 0.f;
    for (int i = t; i < 512; i += 128) {
        float d = sg[i] - muI; v1 += d * d;
        d = sh[i] - muH; v2 += d * d;
    }
    float rsI = rsqrtf(blockSum(v1, red, t, 4) * (1.f / 512.f) + LN_EPS);
    float rsH = rsqrtf(blockSum(v2, red, t, 4) * (1.f / 512.f) + LN_EPS);
    __syncthreads();

    for (int i = t; i < 512; i += 128) {
        float g = (sg[i] - muI) * rsI * a_ln_i_w[i] + a_ln_i_b[i]
                + (sh[i] - muH) * rsH * a_ln_h_w[i] + a_ln_h_b[i];
        sg[i] = g;
    }
    __syncthreads();

    float ac   = total_c[(size_t)b * THW + 1024 + t];
    float cpre = sigf(sg[128 + t]) * ac + sigf(sg[t]) * tanhf(sg[256 + t]);
    float mc = blockSum(cpre, red, t, 4) * (1.f / 128.f);
    float dc = cpre - mc;
    float vc = blockSum(dc * dc, red, t, 4) * (1.f / 128.f);
    float acy = dc * rsqrtf(vc + LN_EPS) * a_ln_c_w[t] + a_ln_c_b[t];
    float ada = sigf(sg[384 + t]) * tanhf(acy);
    sada[t] = ada;
    if (writeFull) {
        out[OFF_H + (size_t)b * THW + 1024 + t] = ada;
        out[OFF_C + (size_t)b * THW + 1024 + t] = acy;
    }
    __syncthreads();

    const float* wz = norm_zw_w + (size_t)t * 128;
    const float* wb = bias_zb_w + (size_t)t * 128;
    float az = 0.f, ab = 0.f;
    #pragma unroll 4
    for (int a = 0; a < 128; a++) { float av = sada[a]; az += av * wz[a]; ab += av * wb[a]; }
    zw_out[(size_t)b * 128 + t] = az + norm_zw_b[t];
    zb_out[(size_t)b * 128 + t] = ab;
}

__global__ __launch_bounds__(256)
void main_pointwise(const float* __restrict__ ing, const float* __restrict__ hidg,
                    const float* __restrict__ total_c,
                    const float* __restrict__ ln_i_w, const float* __restrict__ ln_i_b,
                    const float* __restrict__ ln_h_w, const float* __restrict__ ln_h_b,
                    const float* __restrict__ ln_c_w, const float* __restrict__ ln_c_b,
                    float* __restrict__ out, int writeFull)
{
    __shared__ float sIn[4096];
    __shared__ float sHid[4096];
    __shared__ float red[8];
    const int b = blockIdx.x;
    const int t = threadIdx.x;

    const float4* pi = (const float4*)(ing  + (size_t)b * 4096);
    const float4* ph = (const float4*)(hidg + (size_t)b * 4096);
    for (int i = t; i < 1024; i += 256) {
        ((float4*)sIn)[i]  = pi[i];
        ((float4*)sHid)[i] = ph[i];
    }
    __syncthreads();

    float v1 = 0.f, v2 = 0.f;
    for (int i = t; i < 4096; i += 256) { v1 += sIn[i]; v2 += sHid[i]; }
    float muI = blockSum(v1, red, t, 8) * (1.f / 4096.f);
    float muH = blockSum(v2, red, t, 8) * (1.f / 4096.f);
    v1 = 0.f; v2 = 0.f;
    for (int i = t; i < 4096; i += 256) {
        float d = sIn[i] - muI; v1 += d * d;
        d = sHid[i] - muH; v2 += d * d;
    }
    float rsI = rsqrtf(blockSum(v1, red, t, 8) * (1.f / 4096.f) + LN_EPS);
    float rsH = rsqrtf(blockSum(v2, red, t, 8) * (1.f / 4096.f) + LN_EPS);
    __syncthreads();

    for (int mI = t; mI < 4096; mI += 256) {
        float g = (sIn[mI]  - muI) * rsI * ln_i_w[mI] + ln_i_b[mI]
                + (sHid[mI] - muH) * rsH * ln_h_w[mI] + ln_h_b[mI];
        sIn[mI] = g;
    }
    __syncthreads();

    for (int h = t; h < 1024; h += 256) {
        float gi = sIn[h], gj = sIn[1024 + h], gf = sIn[2048 + h], go = sIn[3072 + h];
        float cx = total_c[(size_t)b * THW + h];
        float cpre = sigf(gf) * cx + sigf(gi) * tanhf(gj);
        sHid[h] = cpre;
        sHid[1024 + h] = go;
    }
    __syncthreads();

    v1 = 0.f;
    for (int h = t; h < 1024; h += 256) v1 += sHid[h];
    float mc = blockSum(v1, red, t, 8) * (1.f / 1024.f);
    v1 = 0.f;
    for (int h = t; h < 1024; h += 256) { float d = sHid[h] - mc; v1 += d * d; }
    float rc = rsqrtf(blockSum(v1, red, t, 8) * (1.f / 1024.f) + LN_EPS);

    for (int h = t; h < 1024; h += 256) {
        float cy = (sHid[h] - mc) * rc * ln_c_w[h] + ln_c_b[h];
        float hy = sigf(sHid[1024 + h]) * tanhf(cy);
        out[(size_t)b * 1024 + h] = hy;
        if (writeFull) {
            out[OFF_H + (size_t)b * THW + h] = hy;
            out[OFF_C + (size_t)b * THW + h] = cy;
        }
    }
}

// ---------------- launch ----------------
extern "C" void kernel_launch(void* const* d_in, const int* in_sizes, int n_in,
                              void* d_out, int out_size)
{
    const float* x           = (const float*)d_in[0];
    const float* total_h     = (const float*)d_in[1];
    const float* total_c     = (const float*)d_in[2];
    const float* w_ih        = (const float*)d_in[3];
    const float* w_hh        = (const float*)d_in[4];
    const float* b_ih        = (const float*)d_in[5];
    const float* b_hh        = (const float*)d_in[6];
    const float* ln_i_w      = (const float*)d_in[7];
    const float* ln_i_b      = (const float*)d_in[8];
    const float* ln_h_w      = (const float*)d_in[9];
    const float* ln_h_b      = (const float*)d_in[10];
    const float* ln_c_w      = (const float*)d_in[11];
    const float* ln_c_b      = (const float*)d_in[12];
    const float* norm_zw_w   = (const float*)d_in[13];
    const float* norm_zw_b   = (const float*)d_in[14];
    const float* norm_alpha_w= (const float*)d_in[15];
    const float* bias_zb_w   = (const float*)d_in[16];
    const float* bias_beta_w = (const float*)d_in[17];
    const float* a_w_ih      = (const float*)d_in[18];
    const float* a_w_hh      = (const float*)d_in[19];
    const float* a_ln_i_w    = (const float*)d_in[20];
    const float* a_ln_i_b    = (const float*)d_in[21];
    const float* a_ln_h_w    = (const float*)d_in[22];
    const float* a_ln_h_b    = (const float*)d_in[23];
    const float* a_ln_c_w    = (const float*)d_in[24];
    const float* a_ln_c_b    = (const float*)d_in[25];
    float* out = (float*)d_out;

    const int writeFull = (size_t)out_size >= OUT_FULL_SIZE ? 1 : 0;

    __nv_bfloat16 *xh_hi, *xh_lo, *wm_hi, *wm_lo, *awih_hi, *awih_lo, *ah_hi, *ah_lo, *awhh_hi, *awhh_lo;
    float *igpre, *hgpre, *zw, *zb, *gates;
    cudaGetSymbolAddress((void**)&xh_hi, g_xh_hi);     cudaGetSymbolAddress((void**)&xh_lo, g_xh_lo);
    cudaGetSymbolAddress((void**)&wm_hi, g_wm_hi);     cudaGetSymbolAddress((void**)&wm_lo, g_wm_lo);
    cudaGetSymbolAddress((void**)&awih_hi, g_awih_hi); cudaGetSymbolAddress((void**)&awih_lo, g_awih_lo);
    cudaGetSymbolAddress((void**)&ah_hi, g_ah_hi);     cudaGetSymbolAddress((void**)&ah_lo, g_ah_lo);
    cudaGetSymbolAddress((void**)&awhh_hi, g_awhh_hi); cudaGetSymbolAddress((void**)&awhh_lo, g_awhh_lo);
    cudaGetSymbolAddress((void**)&igpre, g_igpre);     cudaGetSymbolAddress((void**)&hgpre, g_hgpre);
    cudaGetSymbolAddress((void**)&zw, g_zw);           cudaGetSymbolAddress((void**)&zb, g_zb);
    cudaGetSymbolAddress((void**)&gates, g_gates);

    cudaFuncSetAttribute(gemm_hmma<true, false>,  cudaFuncAttributeMaxDynamicSharedMemorySize, SMEM_SZ);
    cudaFuncSetAttribute(gemm_hmma<false, true>,  cudaFuncAttributeMaxDynamicSharedMemorySize, SMEM_SZ);

    // launch 0: weight splits (w_ih, w_hh)
    split_w<<<dim3(2048, 1, 2), 256>>>(w_ih, w_hh, wm_hi, wm_lo);
    // launch 1: x / hx splits
    split_xh<<<dim3(2048, 1, 2), 256>>>(x, total_h, xh_hi, xh_lo);
    // launch 2: ah + adapter weights
    split_small<<<800, 256>>>(total_h, a_w_ih, a_w_hh,
                              ah_hi, ah_lo, awih_hi, awih_lo, awhh_hi, awhh_lo);

    // launch 3: both adapter GEMMs (z=0: xh@awih K=2048 -> igpre; z=1: ah@awhh K=128 -> hgpre)
    gemm_hmma<false, true><<<dim3(4, 32, 2), 256, SMEM_SZ>>>(
        xh_hi, xh_lo, 2048, 0, awih_hi, awih_lo, 0,
        igpre, 512, 0, 2048,
        ah_hi, ah_lo, 128, awhh_hi, awhh_lo, hgpre, 512, 128,
        nullptr, nullptr, nullptr, nullptr, nullptr, nullptr);

    // launch 4: adapter pointwise -> ada/acy + zw/zb
    adapter_pointwise<<<Bsz, 128>>>(
        igpre, hgpre, total_c,
        a_ln_i_w, a_ln_i_b, a_ln_h_w, a_ln_h_b, a_ln_c_w, a_ln_c_b,
        norm_zw_w, norm_zw_b, bias_zb_w,
        zw, zb, out, writeFull);

    // launch 5 (ncu -s 5 lands here): main GEMMs + fused alpha/beta epilogue
    gemm_hmma<true, false><<<dim3(32, 32, 2), 256, SMEM_SZ>>>(
        xh_hi, xh_lo, 2048, 1024, wm_hi, wm_lo, (long)4096 * 1024,
        gates, 4096, (long)4096 * 4096, 1024,
        nullptr, nullptr, 0, nullptr, nullptr, nullptr, 0, 0,
        norm_alpha_w, bias_beta_w, zw, zb, b_ih, b_hh);

    // launch 6: main pointwise
    main_pointwise<<<Bsz, 256>>>(
        gates, gates + (size_t)4096 * 4096, total_c,
        ln_i_w, ln_i_b, ln_h_w, ln_h_b, ln_c_w, ln_c_b,
        out, writeFull);
}

// round 5
// speedup vs baseline: 4.6428x; 1.5770x over previous
#include <cuda_runtime.h>
#include <cuda_bf16.h>
#include <math.h>
#include <stdint.h>

#define Bsz   4096
#define THW   1152
#define LN_EPS 1e-5f

#define OFF_H ((size_t)Bsz * 1024)
#define OFF_C (OFF_H + (size_t)Bsz * THW)
#define OUT_FULL_SIZE (OFF_C + (size_t)Bsz * THW)

// ---------------- scratch ----------------
__device__ __nv_bfloat16 g_xh_hi[(size_t)Bsz * 2048];
__device__ __nv_bfloat16 g_xh_lo[(size_t)Bsz * 2048];
__device__ __nv_bfloat16 g_wm_hi[(size_t)2 * 4096 * 1024];
__device__ __nv_bfloat16 g_wm_lo[(size_t)2 * 4096 * 1024];
__device__ __nv_bfloat16 g_awih_hi[(size_t)512 * 2048];
__device__ __nv_bfloat16 g_awih_lo[(size_t)512 * 2048];
__device__ __nv_bfloat16 g_ah_hi[(size_t)Bsz * 128];
__device__ __nv_bfloat16 g_ah_lo[(size_t)Bsz * 128];
__device__ __nv_bfloat16 g_awhh_hi[(size_t)512 * 128];
__device__ __nv_bfloat16 g_awhh_lo[(size_t)512 * 128];
__device__ __nv_bfloat16 g_ada_hi[(size_t)Bsz * 128];
__device__ __nv_bfloat16 g_ada_lo[(size_t)Bsz * 128];
__device__ __nv_bfloat16 g_nw_hi[(size_t)256 * 128];
__device__ __nv_bfloat16 g_nw_lo[(size_t)256 * 128];
__device__ float g_igpre[(size_t)Bsz * 512];
__device__ float g_hgpre[(size_t)Bsz * 512];
__device__ float g_zwzb[(size_t)Bsz * 256];
__device__ float g_gates[(size_t)2 * Bsz * 4096];

// ---------------- PTX helpers ----------------
__device__ __forceinline__ uint32_t smem_u32(const void* p) {
    uint32_t a;
    asm("{ .reg .u64 t; cvta.to.shared.u64 t, %1; cvt.u32.u64 %0, t; }" : "=r"(a) : "l"(p));
    return a;
}
__device__ __forceinline__ void cp_async16(uint32_t smaddr, const void* gaddr) {
    asm volatile("cp.async.cg.shared.global [%0], [%1], 16;" :: "r"(smaddr), "l"(gaddr) : "memory");
}
#define CP_COMMIT() asm volatile("cp.async.commit_group;" ::: "memory")
#define CP_WAIT(n)  asm volatile("cp.async.wait_group %0;" :: "n"(n) : "memory")

__device__ __forceinline__ void ldmat4(uint32_t* r, uint32_t addr) {
    asm volatile("ldmatrix.sync.aligned.m8n8.x4.shared.b16 {%0,%1,%2,%3}, [%4];"
        : "=r"(r[0]), "=r"(r[1]), "=r"(r[2]), "=r"(r[3]) : "r"(addr));
}
__device__ __forceinline__ void mma16816(float* c, const uint32_t* a, const uint32_t* b) {
    asm volatile("mma.sync.aligned.m16n8k16.row.col.f32.bf16.bf16.f32 "
        "{%0,%1,%2,%3}, {%4,%5,%6,%7}, {%8,%9}, {%0,%1,%2,%3};"
        : "+f"(c[0]), "+f"(c[1]), "+f"(c[2]), "+f"(c[3])
        : "r"(a[0]), "r"(a[1]), "r"(a[2]), "r"(a[3]), "r"(b[0]), "r"(b[1]));
}

// ---------------- fp32 -> bf16 hi/lo split ----------------
__device__ __forceinline__ void split8_do(const float* src, int srcLd,
                                          __nv_bfloat16* hi, __nv_bfloat16* lo,
                                          int dstLd, int w8, int idx)
{
    const int r = idx / w8, c = (idx - r * w8) * 8;
    const float* s = src + (size_t)r * srcLd + c;
    float4 v0 = *(const float4*)s;
    float4 v1 = *(const float4*)(s + 4);
    float f[8] = { v0.x, v0.y, v0.z, v0.w, v1.x, v1.y, v1.z, v1.w };
    __nv_bfloat16 h[8], l[8];
    #pragma unroll
    for (int i = 0; i < 8; ++i) {
        h[i] = __float2bfloat16(f[i]);
        l[i] = __float2bfloat16(f[i] - __bfloat162float(h[i]));
    }
    *(uint4*)(hi + (size_t)r * dstLd + c) = *(uint4*)h;
    *(uint4*)(lo + (size_t)r * dstLd + c) = *(uint4*)l;
}

__global__ __launch_bounds__(256)
void split_w(const float* __restrict__ w_ih, const float* __restrict__ w_hh,
             __nv_bfloat16* __restrict__ hi, __nv_bfloat16* __restrict__ lo)
{
    int idx = blockIdx.x * 256 + threadIdx.x;
    const float* src = blockIdx.z ? w_hh : w_ih;
    size_t off = (size_t)blockIdx.z * 4096 * 1024;
    split8_do(src, 1024, hi + off, lo + off, 1024, 128, idx);
}

__global__ __launch_bounds__(256)
void split_misc(const float* __restrict__ x, const float* __restrict__ total_h,
                const float* __restrict__ a_w_ih, const float* __restrict__ a_w_hh,
                const float* __restrict__ norm_zw_w, const float* __restrict__ bias_zb_w,
                __nv_bfloat16* __restrict__ xh_hi, __nv_bfloat16* __restrict__ xh_lo,
                __nv_bfloat16* __restrict__ ah_hi, __nv_bfloat16* __restrict__ ah_lo,
                __nv_bfloat16* __restrict__ awih_hi, __nv_bfloat16* __restrict__ awih_lo,
                __nv_bfloat16* __restrict__ awhh_hi, __nv_bfloat16* __restrict__ awhh_lo,
                __nv_bfloat16* __restrict__ nw_hi, __nv_bfloat16* __restrict__ nw_lo)
{
    const int blk = blockIdx.x;
    const int t = threadIdx.x;
    if (blk < 2048)      split8_do(x, 1024, xh_hi, xh_lo, 2048, 128, blk * 256 + t);
    else if (blk < 4096) split8_do(total_h, THW, xh_hi + 1024, xh_lo + 1024, 2048, 128, (blk - 2048) * 256 + t);
    else if (blk < 4352) split8_do(total_h + 1024, THW, ah_hi, ah_lo, 128, 16, (blk - 4096) * 256 + t);
    else if (blk < 4864) split8_do(a_w_ih, 2048, awih_hi, awih_lo, 2048, 256, (blk - 4352) * 256 + t);
    else if (blk < 4896) split8_do(a_w_hh, 128, awhh_hi, awhh_lo, 128, 16, (blk - 4864) * 256 + t);
    else if (blk < 4904) split8_do(norm_zw_w, 128, nw_hi, nw_lo, 128, 16, (blk - 4896) * 256 + t);
    else                 split8_do(bias_zb_w, 128, nw_hi + 128 * 128, nw_lo + 128 * 128, 128, 16, (blk - 4904) * 256 + t);
}

// ---------------- HMMA bf16x3 GEMM v2: 512 thr, tile 128(M)x256(N), Kc=64, 2-stage ----
#define STG_BYTES 98304
#define SMEM_SZ   (2 * STG_BYTES)

template<bool EPI, bool DUAL>
__global__ __launch_bounds__(512, 1)
void gemm_hmma(const __nv_bfloat16* __restrict__ Ahi_, const __nv_bfloat16* __restrict__ Alo_,
               int lda_, int aZoff,
               const __nv_bfloat16* __restrict__ Bhi_, const __nv_bfloat16* __restrict__ Blo_,
               long bZ,
               float* __restrict__ C_, int ldc_, long cZ, int K_,
               const __nv_bfloat16* __restrict__ A2hi, const __nv_bfloat16* __restrict__ A2lo,
               int lda2,
               const __nv_bfloat16* __restrict__ B2hi, const __nv_bfloat16* __restrict__ B2lo,
               float* __restrict__ C2, int ldc2, int K2,
               const float* __restrict__ alphaW, const float* __restrict__ betaW,
               const float* __restrict__ zwzb, const float* __restrict__ nzb,
               const float* __restrict__ bias0, const float* __restrict__ bias1)
{
    extern __shared__ char smem[];
    const uint32_t sb = smem_u32(smem);

    const int tid  = threadIdx.x;
    const int lane = tid & 31;
    const int wid  = tid >> 5;
    const int wm   = wid >> 2;          // 0..3 -> 32 M rows
    const int wn   = wid & 3;           // 0..3 -> 64 N cols
    const int m0 = blockIdx.y * 128;
    const int n0 = blockIdx.x * 256;
    const int z  = blockIdx.z;

    const __nv_bfloat16 *Ahi, *Alo, *Bhi, *Blo;
    float* C;
    int lda, ldc, K;
    if (DUAL && z == 1) {
        Ahi = A2hi; Alo = A2lo; lda = lda2;
        Bhi = B2hi; Blo = B2lo;
        C = C2; ldc = ldc2; K = K2;
    } else {
        Ahi = Ahi_ + (size_t)z * aZoff; Alo = Alo_ + (size_t)z * aZoff; lda = lda_;
        Bhi = Bhi_ + (size_t)z * bZ;    Blo = Blo_ + (size_t)z * bZ;
        C = C_ + (size_t)z * cZ; ldc = ldc_; K = K_;
    }

    float acc[2][8][4];
    #pragma unroll
    for (int i = 0; i < 2; i++)
        #pragma unroll
        for (int j = 0; j < 8; j++)
            #pragma unroll
            for (int q = 0; q < 4; q++) acc[i][j][q] = 0.f;

    const int nCh = K >> 6;
    const int ldRow = tid >> 3;          // 0..63
    const int ldSeg = tid & 7;

    auto load_stage = [&](int chunk, int buf) {
        const uint32_t sbase = sb + buf * STG_BYTES;
        const int kcol = chunk * 64;
        #pragma unroll
        for (int it = 0; it < 2; ++it) {
            const int row = ldRow + it * 64;
            const uint32_t so = (row << 7) + ((ldSeg ^ (row & 7)) << 4);
            const size_t ga = (size_t)(m0 + row) * lda + kcol + ldSeg * 8;
            cp_async16(sbase + so,         Ahi + ga);
            cp_async16(sbase + 16384 + so, Alo + ga);
        }
        #pragma unroll
        for (int it = 0; it < 4; ++it) {
            const int row = ldRow + it * 64;
            const uint32_t so = (row << 7) + ((ldSeg ^ (row & 7)) << 4);
            const size_t gb = (size_t)(n0 + row) * K + kcol + ldSeg * 8;
            cp_async16(sbase + 32768 + so, Bhi + gb);
            cp_async16(sbase + 65536 + so, Blo + gb);
        }
    };

    load_stage(0, 0); CP_COMMIT();
    load_stage(1, 1); CP_COMMIT();

    for (int c = 0; c < nCh; ++c) {
        CP_WAIT(1);
        __syncthreads();

        const int buf = c & 1;
        const uint32_t aHiB = sb + buf * STG_BYTES;
        const uint32_t aLoB = aHiB + 16384;
        const uint32_t bHiB = aHiB + 32768;
        const uint32_t bLoB = aHiB + 65536;

        #pragma unroll
        for (int ks = 0; ks < 4; ++ks) {
            uint32_t ahi[2][4], alo[2][4];
            const int rA = wm * 32 + (lane & 15);
            #pragma unroll
            for (int mi = 0; mi < 2; ++mi) {
                const int row = rA + mi * 16;
                const uint32_t ad = (uint32_t)(row << 7) + (uint32_t)((((ks * 2) + (lane >> 4)) ^ (row & 7)) << 4);
                ldmat4(ahi[mi], aHiB + ad);
                ldmat4(alo[mi], aLoB + ad);
            }
            #pragma unroll
            for (int h = 0; h < 2; ++h) {
                uint32_t bhi[4][2], blo[4][2];
                #pragma unroll
                for (int p = 0; p < 2; ++p) {
                    const int P = h * 2 + p;
                    const int mi2 = lane >> 3;
                    const int row = wn * 64 + (P * 2 + (mi2 >> 1)) * 8 + (lane & 7);
                    const uint32_t ad = (uint32_t)(row << 7) + (uint32_t)((((ks * 2) + (mi2 & 1)) ^ (row & 7)) << 4);
                    ldmat4(&bhi[p * 2][0], bHiB + ad);
                    ldmat4(&blo[p * 2][0], bLoB + ad);
                }
                #pragma unroll
                for (int mi = 0; mi < 2; ++mi)
                    #pragma unroll
                    for (int nj = 0; nj < 4; ++nj) {
                        mma16816(acc[mi][h * 4 + nj], ahi[mi], bhi[nj]);
                        mma16816(acc[mi][h * 4 + nj], ahi[mi], blo[nj]);
                        mma16816(acc[mi][h * 4 + nj], alo[mi], bhi[nj]);
                    }
            }
        }
        __syncthreads();
        if (c + 2 < nCh) load_stage(c + 2, buf);
        CP_COMMIT();
    }

    CP_WAIT(0);
    __syncthreads();

    if (EPI) {
        // epilogue tables (reuse stage smem): bf16 hi/lo rows padded to 48B
        __nv_bfloat16* zwHi = (__nv_bfloat16*)(smem);
        __nv_bfloat16* zwLo = (__nv_bfloat16*)(smem + 6144);
        __nv_bfloat16* zbHi = (__nv_bfloat16*)(smem + 12288);
        __nv_bfloat16* zbLo = (__nv_bfloat16*)(smem + 18432);
        __nv_bfloat16* aWHi = (__nv_bfloat16*)(smem + 24576);
        __nv_bfloat16* aWLo = (__nv_bfloat16*)(smem + 36864);
        __nv_bfloat16* bWHi = (__nv_bfloat16*)(smem + 49152);
        __nv_bfloat16* bWLo = (__nv_bfloat16*)(smem + 61440);
        float* biasS = (float*)(smem + 73728);

        const int s = 4 * z + (n0 >> 10);
        const int hbase = n0 & 1023;
        for (int i = tid; i < 2048; i += 512) {
            const int r = i >> 4, p = i & 15;
            float v = zwzb[(size_t)(m0 + r) * 256 + s * 16 + p] + nzb[s * 16 + p];
            __nv_bfloat16 h = __float2bfloat16(v);
            zwHi[r * 24 + p] = h; zwLo[r * 24 + p] = __float2bfloat16(v - __bfloat162float(h));
            v = zwzb[(size_t)(m0 + r) * 256 + 128 + s * 16 + p];
            h = __float2bfloat16(v);
            zbHi[r * 24 + p] = h; zbLo[r * 24 + p] = __float2bfloat16(v - __bfloat162float(h));
        }
        for (int i = tid; i < 4096; i += 512) {
            const int r = i >> 4, p = i & 15;
            float v = alphaW[((size_t)s * 1024 + hbase + r) * 16 + p];
            __nv_bfloat16 h = __float2bfloat16(v);
            aWHi[r * 24 + p] = h; aWLo[r * 24 + p] = __float2bfloat16(v - __bfloat162float(h));
            v = betaW[((size_t)s * 1024 + hbase + r) * 16 + p];
            h = __float2bfloat16(v);
            bWHi[r * 24 + p] = h; bWLo[r * 24 + p] = __float2bfloat16(v - __bfloat162float(h));
        }
        if (tid < 256) biasS[tid] = (z ? bias1 : bias0)[n0 + tid];
        __syncthreads();

        const int rA = wm * 32 + (lane & 15);
        const uint32_t segOff = (lane >> 4) * 16;
        const int offB = (lane & 3) * 4;

        // ---- alpha: eacc = zw @ aW^T (bf16x3), acc *= eacc ----
        {
            uint32_t fAh[2][4], fAl[2][4];
            #pragma unroll
            for (int mi = 0; mi < 2; ++mi) {
                const int row = rA + mi * 16;
                ldmat4(fAh[mi], sb + 0    + row * 48 + segOff);
                ldmat4(fAl[mi], sb + 6144 + row * 48 + segOff);
            }
            #pragma unroll
            for (int h = 0; h < 2; ++h) {
                float eacc[2][4][4];
                #pragma unroll
                for (int mi = 0; mi < 2; ++mi)
                    #pragma unroll
                    for (int nj = 0; nj < 4; ++nj)
                        #pragma unroll
                        for (int q = 0; q < 4; ++q) eacc[mi][nj][q] = 0.f;
                #pragma unroll
                for (int nj = 0; nj < 4; ++nj) {
                    const int row = wn * 64 + (h * 4 + nj) * 8 + (lane >> 2);
                    uint32_t bh[2], bl[2];
                    bh[0] = *(const uint32_t*)((const char*)aWHi + row * 48 + offB);
                    bh[1] = *(const uint32_t*)((const char*)aWHi + row * 48 + offB + 16);
                    bl[0] = *(const uint32_t*)((const char*)aWLo + row * 48 + offB);
                    bl[1] = *(const uint32_t*)((const char*)aWLo + row * 48 + offB + 16);
                    #pragma unroll
                    for (int mi = 0; mi < 2; ++mi) {
                        mma16816(eacc[mi][nj], fAh[mi], bh);
                        mma16816(eacc[mi][nj], fAh[mi], bl);
                        mma16816(eacc[mi][nj], fAl[mi], bh);
                    }
                }
                #pragma unroll
                for (int mi = 0; mi < 2; ++mi)
                    #pragma unroll
                    for (int nj = 0; nj < 4; ++nj)
                        #pragma unroll
                        for (int q = 0; q < 4; ++q) acc[mi][h * 4 + nj][q] *= eacc[mi][nj][q];
            }
        }
        // ---- beta: eacc = zb @ bW^T (bf16x3), acc += eacc ----
        {
            uint32_t fAh[2][4], fAl[2][4];
            #pragma unroll
            for (int mi = 0; mi < 2; ++mi) {
                const int row = rA + mi * 16;
                ldmat4(fAh[mi], sb + 12288 + row * 48 + segOff);
                ldmat4(fAl[mi], sb + 18432 + row * 48 + segOff);
            }
            #pragma unroll
            for (int h = 0; h < 2; ++h) {
                float eacc[2][4][4];
                #pragma unroll
                for (int mi = 0; mi < 2; ++mi)
                    #pragma unroll
                    for (int nj = 0; nj < 4; ++nj)
                        #pragma unroll
                        for (int q = 0; q < 4; ++q) eacc[mi][nj][q] = 0.f;
                #pragma unroll
                for (int nj = 0; nj < 4; ++nj) {
                    const int row = wn * 64 + (h * 4 + nj) * 8 + (lane >> 2);
                    uint32_t bh[2], bl[2];
                    bh[0] = *(const uint32_t*)((const char*)bWHi + row * 48 + offB);
                    bh[1] = *(const uint32_t*)((const char*)bWHi + row * 48 + offB + 16);
                    bl[0] = *(const uint32_t*)((const char*)bWLo + row * 48 + offB);
                    bl[1] = *(const uint32_t*)((const char*)bWLo + row * 48 + offB + 16);
                    #pragma unroll
                    for (int mi = 0; mi < 2; ++mi) {
                        mma16816(eacc[mi][nj], fAh[mi], bh);
                        mma16816(eacc[mi][nj], fAh[mi], bl);
                        mma16816(eacc[mi][nj], fAl[mi], bh);
                    }
                }
                #pragma unroll
                for (int mi = 0; mi < 2; ++mi)
                    #pragma unroll
                    for (int nj = 0; nj < 4; ++nj)
                        #pragma unroll
                        for (int q = 0; q < 4; ++q) acc[mi][h * 4 + nj][q] += eacc[mi][nj][q];
            }
        }

        #pragma unroll
        for (int mi = 0; mi < 2; ++mi) {
            const int row = m0 + wm * 32 + mi * 16 + (lane >> 2);
            #pragma unroll
            for (int ni = 0; ni < 8; ++ni) {
                const int cl = wn * 64 + ni * 8 + (lane & 3) * 2;
                const float b0 = biasS[cl], b1 = biasS[cl + 1];
                *(float2*)(C + (size_t)row * ldc + n0 + cl)       = make_float2(acc[mi][ni][0] + b0, acc[mi][ni][1] + b1);
                *(float2*)(C + (size_t)(row + 8) * ldc + n0 + cl) = make_float2(acc[mi][ni][2] + b0, acc[mi][ni][3] + b1);
            }
        }
    } else {
        #pragma unroll
        for (int mi = 0; mi < 2; ++mi) {
            const int row = m0 + wm * 32 + mi * 16 + (lane >> 2);
            #pragma unroll
            for (int ni = 0; ni < 8; ++ni) {
                const int cl = wn * 64 + ni * 8 + (lane & 3) * 2;
                *(float2*)(C + (size_t)row * ldc + n0 + cl)       = make_float2(acc[mi][ni][0], acc[mi][ni][1]);
                *(float2*)(C + (size_t)(row + 8) * ldc + n0 + cl) = make_float2(acc[mi][ni][2], acc[mi][ni][3]);
            }
        }
    }
}

// ---------------- pointwise ----------------
__device__ __forceinline__ float sigf(float x) { return 1.f / (1.f + expf(-x)); }
__device__ __forceinline__ float blockSum(float v, float* red, int t, int nwarp) {
    #pragma unroll
    for (int o = 16; o > 0; o >>= 1) v += __shfl_xor_sync(0xffffffffu, v, o);
    __syncthreads();
    if ((t & 31) == 0) red[t >> 5] = v;
    __syncthreads();
    float s = 0.f;
    for (int w = 0; w < nwarp; w++) s += red[w];
    return s;
}

__global__ __launch_bounds__(128)
void adapter_pointwise(const float* __restrict__ igpre, const float* __restrict__ hgpre,
                       const float* __restrict__ total_c,
                       const float* __restrict__ a_ln_i_w, const float* __restrict__ a_ln_i_b,
                       const float* __restrict__ a_ln_h_w, const float* __restrict__ a_ln_h_b,
                       const float* __restrict__ a_ln_c_w, const float* __restrict__ a_ln_c_b,
                       __nv_bfloat16* __restrict__ ada_hi, __nv_bfloat16* __restrict__ ada_lo,
                       float* __restrict__ out, int writeFull)
{
    __shared__ float sg[512];
    __shared__ float sh[512];
    __shared__ float red[4];
    const int b = blockIdx.x;
    const int t = threadIdx.x;

    for (int i = t; i < 512; i += 128) {
        sg[i] = igpre[(size_t)b * 512 + i];
        sh[i] = hgpre[(size_t)b * 512 + i];
    }
    __syncthreads();

    float v1 = 0.f, v2 = 0.f;
    for (int i = t; i < 512; i += 128) { v1 += sg[i]; v2 += sh[i]; }
    float muI = blockSum(v1, red, t, 4) * (1.f / 512.f);
    float muH = blockSum(v2, red, t, 4) * (1.f / 512.f);
    v1 = 0.f; v2 = 0.f;
    for (int i = t; i < 512; i += 128) {
        float d = sg[i] - muI; v1 += d * d;
        d = sh[i] - muH; v2 += d * d;
    }
    float rsI = rsqrtf(blockSum(v1, red, t, 4) * (1.f / 512.f) + LN_EPS);
    float rsH = rsqrtf(blockSum(v2, red, t, 4) * (1.f / 512.f) + LN_EPS);
    __syncthreads();

    for (int i = t; i < 512; i += 128) {
        float g = (sg[i] - muI) * rsI * a_ln_i_w[i] + a_ln_i_b[i]
                + (sh[i] - muH) * rsH * a_ln_h_w[i] + a_ln_h_b[i];
        sg[i] = g;
    }
    __syncthreads();

    float ac   = total_c[(size_t)b * THW + 1024 + t];
    float cpre = sigf(sg[128 + t]) * ac + sigf(sg[t]) * tanhf(sg[256 + t]);
    float mc = blockSum(cpre, red, t, 4) * (1.f / 128.f);
    float dc = cpre - mc;
    float vc = blockSum(dc * dc, red, t, 4) * (1.f / 128.f);
    float acy = dc * rsqrtf(vc + LN_EPS) * a_ln_c_w[t] + a_ln_c_b[t];
    float ada = sigf(sg[384 + t]) * tanhf(acy);

    __nv_bfloat16 h = __float2bfloat16(ada);
    ada_hi[(size_t)b * 128 + t] = h;
    ada_lo[(size_t)b * 128 + t] = __float2bfloat16(ada - __bfloat162float(h));
    if (writeFull) {
        out[OFF_H + (size_t)b * THW + 1024 + t] = ada;
        out[OFF_C + (size_t)b * THW + 1024 + t] = acy;
    }
}

__global__ __launch_bounds__(256)
void main_pointwise(const float* __restrict__ ing, const float* __restrict__ hidg,
                    const float* __restrict__ total_c,
                    const float* __restrict__ ln_i_w, const float* __restrict__ ln_i_b,
                    const float* __restrict__ ln_h_w, const float* __restrict__ ln_h_b,
                    const float* __restrict__ ln_c_w, const float* __restrict__ ln_c_b,
                    float* __restrict__ out, int writeFull)
{
    __shared__ float sIn[4096];
    __shared__ float sHid[4096];
    __shared__ float red[8];
    const int b = blockIdx.x;
    const int t = threadIdx.x;

    const float4* pi = (const float4*)(ing  + (size_t)b * 4096);
    const float4* ph = (const float4*)(hidg + (size_t)b * 4096);
    for (int i = t; i < 1024; i += 256) {
        ((float4*)sIn)[i]  = pi[i];
        ((float4*)sHid)[i] = ph[i];
    }
    __syncthreads();

    float v1 = 0.f, v2 = 0.f;
    for (int i = t; i < 4096; i += 256) { v1 += sIn[i]; v2 += sHid[i]; }
    float muI = blockSum(v1, red, t, 8) * (1.f / 4096.f);
    float muH = blockSum(v2, red, t, 8) * (1.f / 4096.f);
    v1 = 0.f; v2 = 0.f;
    for (int i = t; i < 4096; i += 256) {
        float d = sIn[i] - muI; v1 += d * d;
        d = sHid[i] - muH; v2 += d * d;
    }
    float rsI = rsqrtf(blockSum(v1, red, t, 8) * (1.f / 4096.f) + LN_EPS);
    float rsH = rsqrtf(blockSum(v2, red, t, 8) * (1.f / 4096.f) + LN_EPS);
    __syncthreads();

    for (int mI = t; mI < 4096; mI += 256) {
        float g = (sIn[mI]  - muI) * rsI * ln_i_w[mI] + ln_i_b[mI]
                + (sHid[mI] - muH) * rsH * ln_h_w[mI] + ln_h_b[mI];
        sIn[mI] = g;
    }
    __syncthreads();

    for (int h = t; h < 1024; h += 256) {
        float gi = sIn[h], gj = sIn[1024 + h], gf = sIn[2048 + h], go = sIn[3072 + h];
        float cx = total_c[(size_t)b * THW + h];
        float cpre = sigf(gf) * cx + sigf(gi) * tanhf(gj);
        sHid[h] = cpre;
        sHid[1024 + h] = go;
    }
    __syncthreads();

    v1 = 0.f;
    for (int h = t; h < 1024; h += 256) v1 += sHid[h];
    float mc = blockSum(v1, red, t, 8) * (1.f / 1024.f);
    v1 = 0.f;
    for (int h = t; h < 1024; h += 256) { float d = sHid[h] - mc; v1 += d * d; }
    float rc = rsqrtf(blockSum(v1, red, t, 8) * (1.f / 1024.f) + LN_EPS);

    for (int h = t; h < 1024; h += 256) {
        float cy = (sHid[h] - mc) * rc * ln_c_w[h] + ln_c_b[h];
        float hy = sigf(sHid[1024 + h]) * tanhf(cy);
        out[(size_t)b * 1024 + h] = hy;
        if (writeFull) {
            out[OFF_H + (size_t)b * THW + h] = hy;
            out[OFF_C + (size_t)b * THW + h] = cy;
        }
    }
}

// ---------------- launch ----------------
extern "C" void kernel_launch(void* const* d_in, const int* in_sizes, int n_in,
                              void* d_out, int out_size)
{
    const float* x           = (const float*)d_in[0];
    const float* total_h     = (const float*)d_in[1];
    const float* total_c     = (const float*)d_in[2];
    const float* w_ih        = (const float*)d_in[3];
    const float* w_hh        = (const float*)d_in[4];
    const float* b_ih        = (const float*)d_in[5];
    const float* b_hh        = (const float*)d_in[6];
    const float* ln_i_w      = (const float*)d_in[7];
    const float* ln_i_b      = (const float*)d_in[8];
    const float* ln_h_w      = (const float*)d_in[9];
    const float* ln_h_b      = (const float*)d_in[10];
    const float* ln_c_w      = (const float*)d_in[11];
    const float* ln_c_b      = (const float*)d_in[12];
    const float* norm_zw_w   = (const float*)d_in[13];
    const float* norm_zw_b   = (const float*)d_in[14];
    const float* norm_alpha_w= (const float*)d_in[15];
    const float* bias_zb_w   = (const float*)d_in[16];
    const float* bias_beta_w = (const float*)d_in[17];
    const float* a_w_ih      = (const float*)d_in[18];
    const float* a_w_hh      = (const float*)d_in[19];
    const float* a_ln_i_w    = (const float*)d_in[20];
    const float* a_ln_i_b    = (const float*)d_in[21];
    const float* a_ln_h_w    = (const float*)d_in[22];
    const float* a_ln_h_b    = (const float*)d_in[23];
    const float* a_ln_c_w    = (const float*)d_in[24];
    const float* a_ln_c_b    = (const float*)d_in[25];
    float* out = (float*)d_out;

    const int writeFull = (size_t)out_size >= OUT_FULL_SIZE ? 1 : 0;

    __nv_bfloat16 *xh_hi, *xh_lo, *wm_hi, *wm_lo, *awih_hi, *awih_lo, *ah_hi, *ah_lo, *awhh_hi, *awhh_lo;
    __nv_bfloat16 *ada_hi, *ada_lo, *nw_hi, *nw_lo;
    float *igpre, *hgpre, *zwzb, *gates;
    cudaGetSymbolAddress((void**)&xh_hi, g_xh_hi);     cudaGetSymbolAddress((void**)&xh_lo, g_xh_lo);
    cudaGetSymbolAddress((void**)&wm_hi, g_wm_hi);     cudaGetSymbolAddress((void**)&wm_lo, g_wm_lo);
    cudaGetSymbolAddress((void**)&awih_hi, g_awih_hi); cudaGetSymbolAddress((void**)&awih_lo, g_awih_lo);
    cudaGetSymbolAddress((void**)&ah_hi, g_ah_hi);     cudaGetSymbolAddress((void**)&ah_lo, g_ah_lo);
    cudaGetSymbolAddress((void**)&awhh_hi, g_awhh_hi); cudaGetSymbolAddress((void**)&awhh_lo, g_awhh_lo);
    cudaGetSymbolAddress((void**)&ada_hi, g_ada_hi);   cudaGetSymbolAddress((void**)&ada_lo, g_ada_lo);
    cudaGetSymbolAddress((void**)&nw_hi, g_nw_hi);     cudaGetSymbolAddress((void**)&nw_lo, g_nw_lo);
    cudaGetSymbolAddress((void**)&igpre, g_igpre);     cudaGetSymbolAddress((void**)&hgpre, g_hgpre);
    cudaGetSymbolAddress((void**)&zwzb, g_zwzb);       cudaGetSymbolAddress((void**)&gates, g_gates);

    cudaFuncSetAttribute(gemm_hmma<true, false>,  cudaFuncAttributeMaxDynamicSharedMemorySize, SMEM_SZ);
    cudaFuncSetAttribute(gemm_hmma<false, true>,  cudaFuncAttributeMaxDynamicSharedMemorySize, SMEM_SZ);
    cudaFuncSetAttribute(gemm_hmma<false, false>, cudaFuncAttributeMaxDynamicSharedMemorySize, SMEM_SZ);

    // 0: weight splits
    split_w<<<dim3(2048, 1, 2), 256>>>(w_ih, w_hh, wm_hi, wm_lo);
    // 1: everything else
    split_misc<<<4912, 256>>>(x, total_h, a_w_ih, a_w_hh, norm_zw_w, bias_zb_w,
                              xh_hi, xh_lo, ah_hi, ah_lo, awih_hi, awih_lo,
                              awhh_hi, awhh_lo, nw_hi, nw_lo);

    // 2: adapter GEMMs (z=0: xh@awih K=2048 -> igpre; z=1: ah@awhh K=128 -> hgpre)
    gemm_hmma<false, true><<<dim3(2, 32, 2), 512, SMEM_SZ>>>(
        xh_hi, xh_lo, 2048, 0, awih_hi, awih_lo, 0,
        igpre, 512, 0, 2048,
        ah_hi, ah_lo, 128, awhh_hi, awhh_lo, hgpre, 512, 128,
        nullptr, nullptr, nullptr, nullptr, nullptr, nullptr);

    // 3: adapter pointwise -> ada (hi/lo) + outputs
    adapter_pointwise<<<Bsz, 128>>>(
        igpre, hgpre, total_c,
        a_ln_i_w, a_ln_i_b, a_ln_h_w, a_ln_h_b, a_ln_c_w, a_ln_c_b,
        ada_hi, ada_lo, out, writeFull);

    // 4: zwzb GEMM: [zw|zb] = ada @ [norm_zw_w; bias_zb_w]^T  (4096x256x128)
    gemm_hmma<false, false><<<dim3(1, 32, 1), 512, SMEM_SZ>>>(
        ada_hi, ada_lo, 128, 0, nw_hi, nw_lo, 0,
        zwzb, 256, 0, 128,
        nullptr, nullptr, 0, nullptr, nullptr, nullptr, 0, 0,
        nullptr, nullptr, nullptr, nullptr, nullptr, nullptr);

    // 5 (ncu -s 5): main GEMMs + fused alpha/beta epilogue
    gemm_hmma<true, false><<<dim3(16, 32, 2), 512, SMEM_SZ>>>(
        xh_hi, xh_lo, 2048, 1024, wm_hi, wm_lo, (long)4096 * 1024,
        gates, 4096, (long)4096 * 4096, 1024,
        nullptr, nullptr, 0, nullptr, nullptr, nullptr, 0, 0,
        norm_alpha_w, bias_beta_w, zwzb, norm_zw_b, b_ih, b_hh);

    // 6: main pointwise
    main_pointwise<<<Bsz, 256>>>(
        gates, gates + (size_t)4096 * 4096, total_c,
        ln_i_w, ln_i_b, ln_h_w, ln_h_b, ln_c_w, ln_c_b,
        out, writeFull);
}

// round 6
// speedup vs baseline: 4.8835x; 1.0518x over previous
#include <cuda_runtime.h>
#include <cuda_bf16.h>
#include <math.h>
#include <stdint.h>

#define Bsz   4096
#define THW   1152
#define LN_EPS 1e-5f

#define OFF_H ((size_t)Bsz * 1024)
#define OFF_C (OFF_H + (size_t)Bsz * THW)
#define OUT_FULL_SIZE (OFF_C + (size_t)Bsz * THW)

// ---------------- scratch ----------------
__device__ __nv_bfloat16 g_xh_hi[(size_t)Bsz * 2048];
__device__ __nv_bfloat16 g_xh_lo[(size_t)Bsz * 2048];
__device__ __nv_bfloat16 g_wm_hi[(size_t)2 * 4096 * 1024];
__device__ __nv_bfloat16 g_wm_lo[(size_t)2 * 4096 * 1024];
__device__ __nv_bfloat16 g_awih_hi[(size_t)512 * 2048];
__device__ __nv_bfloat16 g_awih_lo[(size_t)512 * 2048];
__device__ __nv_bfloat16 g_ah_hi[(size_t)Bsz * 128];
__device__ __nv_bfloat16 g_ah_lo[(size_t)Bsz * 128];
__device__ __nv_bfloat16 g_awhh_hi[(size_t)512 * 128];
__device__ __nv_bfloat16 g_awhh_lo[(size_t)512 * 128];
__device__ __nv_bfloat16 g_zwzbHi[(size_t)Bsz * 256];
__device__ __nv_bfloat16 g_zwzbLo[(size_t)Bsz * 256];
__device__ __nv_bfloat16 g_aWHi[131072];
__device__ __nv_bfloat16 g_aWLo[131072];
__device__ __nv_bfloat16 g_bWHi[131072];
__device__ __nv_bfloat16 g_bWLo[131072];
__device__ float g_nwT[128 * 256];
__device__ float g_igpre[(size_t)Bsz * 512];
__device__ float g_hgpre[(size_t)Bsz * 512];
__device__ float g_gates[(size_t)2 * Bsz * 4096];

// ---------------- PTX helpers ----------------
__device__ __forceinline__ uint32_t smem_u32(const void* p) {
    uint32_t a;
    asm("{ .reg .u64 t; cvta.to.shared.u64 t, %1; cvt.u32.u64 %0, t; }" : "=r"(a) : "l"(p));
    return a;
}
__device__ __forceinline__ void cp_async16(uint32_t smaddr, const void* gaddr) {
    asm volatile("cp.async.cg.shared.global [%0], [%1], 16;" :: "r"(smaddr), "l"(gaddr) : "memory");
}
#define CP_COMMIT() asm volatile("cp.async.commit_group;" ::: "memory")
#define CP_WAIT(n)  asm volatile("cp.async.wait_group %0;" :: "n"(n) : "memory")

__device__ __forceinline__ void ldmat4(uint32_t* r, uint32_t addr) {
    asm volatile("ldmatrix.sync.aligned.m8n8.x4.shared.b16 {%0,%1,%2,%3}, [%4];"
        : "=r"(r[0]), "=r"(r[1]), "=r"(r[2]), "=r"(r[3]) : "r"(addr));
}
__device__ __forceinline__ void mma16816(float* c, const uint32_t* a, const uint32_t* b) {
    asm volatile("mma.sync.aligned.m16n8k16.row.col.f32.bf16.bf16.f32 "
        "{%0,%1,%2,%3}, {%4,%5,%6,%7}, {%8,%9}, {%0,%1,%2,%3};"
        : "+f"(c[0]), "+f"(c[1]), "+f"(c[2]), "+f"(c[3])
        : "r"(a[0]), "r"(a[1]), "r"(a[2]), "r"(a[3]), "r"(b[0]), "r"(b[1]));
}

// ---------------- fp32 -> bf16 hi/lo split ----------------
__device__ __forceinline__ void split8_do(const float* src, int srcLd,
                                          __nv_bfloat16* hi, __nv_bfloat16* lo,
                                          int dstLd, int w8, int idx)
{
    const int r = idx / w8, c = (idx - r * w8) * 8;
    const float* s = src + (size_t)r * srcLd + c;
    float4 v0 = *(const float4*)s;
    float4 v1 = *(const float4*)(s + 4);
    float f[8] = { v0.x, v0.y, v0.z, v0.w, v1.x, v1.y, v1.z, v1.w };
    __nv_bfloat16 h[8], l[8];
    #pragma unroll
    for (int i = 0; i < 8; ++i) {
        h[i] = __float2bfloat16(f[i]);
        l[i] = __float2bfloat16(f[i] - __bfloat162float(h[i]));
    }
    *(uint4*)(hi + (size_t)r * dstLd + c) = *(uint4*)h;
    *(uint4*)(lo + (size_t)r * dstLd + c) = *(uint4*)l;
}

// single launch covering every conversion
__global__ __launch_bounds__(256)
void split_all(const float* __restrict__ w_ih, const float* __restrict__ w_hh,
               const float* __restrict__ x, const float* __restrict__ total_h,
               const float* __restrict__ a_w_ih, const float* __restrict__ a_w_hh,
               const float* __restrict__ norm_alpha_w, const float* __restrict__ bias_beta_w,
               const float* __restrict__ norm_zw_w, const float* __restrict__ bias_zb_w,
               __nv_bfloat16* __restrict__ wm_hi, __nv_bfloat16* __restrict__ wm_lo,
               __nv_bfloat16* __restrict__ xh_hi, __nv_bfloat16* __restrict__ xh_lo,
               __nv_bfloat16* __restrict__ ah_hi, __nv_bfloat16* __restrict__ ah_lo,
               __nv_bfloat16* __restrict__ awih_hi, __nv_bfloat16* __restrict__ awih_lo,
               __nv_bfloat16* __restrict__ awhh_hi, __nv_bfloat16* __restrict__ awhh_lo,
               __nv_bfloat16* __restrict__ aWHi, __nv_bfloat16* __restrict__ aWLo,
               __nv_bfloat16* __restrict__ bWHi, __nv_bfloat16* __restrict__ bWLo,
               float* __restrict__ nwT)
{
    const int blk = blockIdx.x;
    const int t = threadIdx.x;
    if (blk < 2048)       split8_do(w_ih, 1024, wm_hi, wm_lo, 1024, 128, blk * 256 + t);
    else if (blk < 4096)  split8_do(w_hh, 1024, wm_hi + (size_t)4096 * 1024, wm_lo + (size_t)4096 * 1024, 1024, 128, (blk - 2048) * 256 + t);
    else if (blk < 6144)  split8_do(x, 1024, xh_hi, xh_lo, 2048, 128, (blk - 4096) * 256 + t);
    else if (blk < 8192)  split8_do(total_h, THW, xh_hi + 1024, xh_lo + 1024, 2048, 128, (blk - 6144) * 256 + t);
    else if (blk < 8448)  split8_do(total_h + 1024, THW, ah_hi, ah_lo, 128, 16, (blk - 8192) * 256 + t);
    else if (blk < 8960)  split8_do(a_w_ih, 2048, awih_hi, awih_lo, 2048, 256, (blk - 8448) * 256 + t);
    else if (blk < 8992)  split8_do(a_w_hh, 128, awhh_hi, awhh_lo, 128, 16, (blk - 8960) * 256 + t);
    else if (blk < 9056)  split8_do(norm_alpha_w, 131072, aWHi, aWLo, 131072, 16384, (blk - 8992) * 256 + t);
    else if (blk < 9120)  split8_do(bias_beta_w, 131072, bWHi, bWLo, 131072, 16384, (blk - 9056) * 256 + t);
    else {
        int idx = (blk - 9120) * 256 + t;        // 32768 elements
        int a = idx >> 8, j = idx & 255;
        nwT[a * 256 + j] = (j < 128) ? norm_zw_w[j * 128 + a] : bias_zb_w[(j - 128) * 128 + a];
    }
}

// ---------------- HMMA bf16x3 GEMM: 512 thr, tile 128(M)x256(N), Kc=64, 2-stage ----
#define STG_BYTES 98304
#define SMEM_SZ   (2 * STG_BYTES)

template<bool EPI, bool DUAL>
__global__ __launch_bounds__(512, 1)
void gemm_hmma(const __nv_bfloat16* __restrict__ Ahi_, const __nv_bfloat16* __restrict__ Alo_,
               int lda_, int aZoff,
               const __nv_bfloat16* __restrict__ Bhi_, const __nv_bfloat16* __restrict__ Blo_,
               long bZ,
               float* __restrict__ C_, int ldc_, long cZ, int K_,
               const __nv_bfloat16* __restrict__ A2hi, const __nv_bfloat16* __restrict__ A2lo,
               int lda2,
               const __nv_bfloat16* __restrict__ B2hi, const __nv_bfloat16* __restrict__ B2lo,
               float* __restrict__ C2, int ldc2, int K2,
               const __nv_bfloat16* __restrict__ zwzbHiG, const __nv_bfloat16* __restrict__ zwzbLoG,
               const __nv_bfloat16* __restrict__ aWHiG, const __nv_bfloat16* __restrict__ aWLoG,
               const __nv_bfloat16* __restrict__ bWHiG, const __nv_bfloat16* __restrict__ bWLoG,
               const float* __restrict__ bias0, const float* __restrict__ bias1)
{
    extern __shared__ char smem[];
    const uint32_t sb = smem_u32(smem);

    const int tid  = threadIdx.x;
    const int lane = tid & 31;
    const int wid  = tid >> 5;
    const int wm   = wid >> 2;          // 0..3 -> 32 M rows
    const int wn   = wid & 3;           // 0..3 -> 64 N cols
    const int m0 = blockIdx.y * 128;
    const int n0 = blockIdx.x * 256;
    const int z  = blockIdx.z;

    const __nv_bfloat16 *Ahi, *Alo, *Bhi, *Blo;
    float* C;
    int lda, ldc, K;
    if (DUAL && z == 1) {
        Ahi = A2hi; Alo = A2lo; lda = lda2;
        Bhi = B2hi; Blo = B2lo;
        C = C2; ldc = ldc2; K = K2;
    } else {
        Ahi = Ahi_ + (size_t)z * aZoff; Alo = Alo_ + (size_t)z * aZoff; lda = lda_;
        Bhi = Bhi_ + (size_t)z * bZ;    Blo = Blo_ + (size_t)z * bZ;
        C = C_ + (size_t)z * cZ; ldc = ldc_; K = K_;
    }

    float acc[2][8][4];
    #pragma unroll
    for (int i = 0; i < 2; i++)
        #pragma unroll
        for (int j = 0; j < 8; j++)
            #pragma unroll
            for (int q = 0; q < 4; q++) acc[i][j][q] = 0.f;

    const int nCh = K >> 6;
    const int ldRow = tid >> 3;
    const int ldSeg = tid & 7;

    auto load_stage = [&](int chunk, int buf) {
        const uint32_t sbase = sb + buf * STG_BYTES;
        const int kcol = chunk * 64;
        #pragma unroll
        for (int it = 0; it < 2; ++it) {
            const int row = ldRow + it * 64;
            const uint32_t so = (row << 7) + ((ldSeg ^ (row & 7)) << 4);
            const size_t ga = (size_t)(m0 + row) * lda + kcol + ldSeg * 8;
            cp_async16(sbase + so,         Ahi + ga);
            cp_async16(sbase + 16384 + so, Alo + ga);
        }
        #pragma unroll
        for (int it = 0; it < 4; ++it) {
            const int row = ldRow + it * 64;
            const uint32_t so = (row << 7) + ((ldSeg ^ (row & 7)) << 4);
            const size_t gb = (size_t)(n0 + row) * K + kcol + ldSeg * 8;
            cp_async16(sbase + 32768 + so, Bhi + gb);
            cp_async16(sbase + 65536 + so, Blo + gb);
        }
    };

    load_stage(0, 0); CP_COMMIT();
    load_stage(1, 1); CP_COMMIT();

    for (int c = 0; c < nCh; ++c) {
        CP_WAIT(1);
        __syncthreads();

        const int buf = c & 1;
        const uint32_t aHiB = sb + buf * STG_BYTES;
        const uint32_t aLoB = aHiB + 16384;
        const uint32_t bHiB = aHiB + 32768;
        const uint32_t bLoB = aHiB + 65536;

        #pragma unroll
        for (int ks = 0; ks < 4; ++ks) {
            uint32_t ahi[2][4], alo[2][4];
            const int rA = wm * 32 + (lane & 15);
            #pragma unroll
            for (int mi = 0; mi < 2; ++mi) {
                const int row = rA + mi * 16;
                const uint32_t ad = (uint32_t)(row << 7) + (uint32_t)((((ks * 2) + (lane >> 4)) ^ (row & 7)) << 4);
                ldmat4(ahi[mi], aHiB + ad);
                ldmat4(alo[mi], aLoB + ad);
            }
            #pragma unroll
            for (int h = 0; h < 2; ++h) {
                uint32_t bhi[4][2], blo[4][2];
                #pragma unroll
                for (int p = 0; p < 2; ++p) {
                    const int P = h * 2 + p;
                    const int mi2 = lane >> 3;
                    const int row = wn * 64 + (P * 2 + (mi2 >> 1)) * 8 + (lane & 7);
                    const uint32_t ad = (uint32_t)(row << 7) + (uint32_t)((((ks * 2) + (mi2 & 1)) ^ (row & 7)) << 4);
                    ldmat4(&bhi[p * 2][0], bHiB + ad);
                    ldmat4(&blo[p * 2][0], bLoB + ad);
                }
                #pragma unroll
                for (int mi = 0; mi < 2; ++mi)
                    #pragma unroll
                    for (int nj = 0; nj < 4; ++nj) {
                        mma16816(acc[mi][h * 4 + nj], ahi[mi], bhi[nj]);
                        mma16816(acc[mi][h * 4 + nj], ahi[mi], blo[nj]);
                        mma16816(acc[mi][h * 4 + nj], alo[mi], bhi[nj]);
                    }
            }
        }
        __syncthreads();
        if (c + 2 < nCh) load_stage(c + 2, buf);
        CP_COMMIT();
    }

    CP_WAIT(0);
    __syncthreads();

    if (EPI) {
        __nv_bfloat16* zwHi = (__nv_bfloat16*)(smem);
        __nv_bfloat16* zwLo = (__nv_bfloat16*)(smem + 6144);
        __nv_bfloat16* zbHi = (__nv_bfloat16*)(smem + 12288);
        __nv_bfloat16* zbLo = (__nv_bfloat16*)(smem + 18432);
        __nv_bfloat16* aWHi = (__nv_bfloat16*)(smem + 24576);
        __nv_bfloat16* aWLo = (__nv_bfloat16*)(smem + 36864);
        __nv_bfloat16* bWHi = (__nv_bfloat16*)(smem + 49152);
        __nv_bfloat16* bWLo = (__nv_bfloat16*)(smem + 61440);
        float* biasS = (float*)(smem + 73728);

        const int s = 4 * z + (n0 >> 10);
        const int hbase = n0 & 1023;

        // zw / zb tables: prepacked bf16 hi/lo, rows of 16 -> 48B pitch smem
        if (tid < 128) {
            const __nv_bfloat16* sh = zwzbHiG + (size_t)(m0 + tid) * 256 + s * 16;
            const __nv_bfloat16* sl = zwzbLoG + (size_t)(m0 + tid) * 256 + s * 16;
            *(uint4*)((char*)zwHi + tid * 48)      = *(const uint4*)(sh);
            *(uint4*)((char*)zwHi + tid * 48 + 16) = *(const uint4*)(sh + 8);
            *(uint4*)((char*)zwLo + tid * 48)      = *(const uint4*)(sl);
            *(uint4*)((char*)zwLo + tid * 48 + 16) = *(const uint4*)(sl + 8);
            *(uint4*)((char*)zbHi + tid * 48)      = *(const uint4*)(sh + 128);
            *(uint4*)((char*)zbHi + tid * 48 + 16) = *(const uint4*)(sh + 136);
            *(uint4*)((char*)zbLo + tid * 48)      = *(const uint4*)(sl + 128);
            *(uint4*)((char*)zbLo + tid * 48 + 16) = *(const uint4*)(sl + 136);
        }
        // alphaW / betaW tables (256 rows x hi/lo)
        {
            const int r = tid >> 1, half = tid & 1;
            const size_t go = ((size_t)s * 1024 + hbase + r) * 16;
            const __nv_bfloat16* asrc = (half ? aWLoG : aWHiG) + go;
            __nv_bfloat16* adst = half ? aWLo : aWHi;
            *(uint4*)((char*)adst + r * 48)      = *(const uint4*)(asrc);
            *(uint4*)((char*)adst + r * 48 + 16) = *(const uint4*)(asrc + 8);
            const __nv_bfloat16* bsrc = (half ? bWLoG : bWHiG) + go;
            __nv_bfloat16* bdst = half ? bWLo : bWHi;
            *(uint4*)((char*)bdst + r * 48)      = *(const uint4*)(bsrc);
            *(uint4*)((char*)bdst + r * 48 + 16) = *(const uint4*)(bsrc + 8);
        }
        if (tid < 256) biasS[tid] = (z ? bias1 : bias0)[n0 + tid];
        __syncthreads();

        const int rA = wm * 32 + (lane & 15);
        const uint32_t segOff = (lane >> 4) * 16;
        const int offB = (lane & 3) * 4;

        // ---- alpha: eacc = zw @ aW^T (bf16x3), acc *= eacc ----
        {
            uint32_t fAh[2][4], fAl[2][4];
            #pragma unroll
            for (int mi = 0; mi < 2; ++mi) {
                const int row = rA + mi * 16;
                ldmat4(fAh[mi], sb + 0    + row * 48 + segOff);
                ldmat4(fAl[mi], sb + 6144 + row * 48 + segOff);
            }
            #pragma unroll
            for (int h = 0; h < 2; ++h) {
                float eacc[2][4][4];
                #pragma unroll
                for (int mi = 0; mi < 2; ++mi)
                    #pragma unroll
                    for (int nj = 0; nj < 4; ++nj)
                        #pragma unroll
                        for (int q = 0; q < 4; ++q) eacc[mi][nj][q] = 0.f;
                #pragma unroll
                for (int nj = 0; nj < 4; ++nj) {
                    const int row = wn * 64 + (h * 4 + nj) * 8 + (lane >> 2);
                    uint32_t bh[2], bl[2];
                    bh[0] = *(const uint32_t*)((const char*)aWHi + row * 48 + offB);
                    bh[1] = *(const uint32_t*)((const char*)aWHi + row * 48 + offB + 16);
                    bl[0] = *(const uint32_t*)((const char*)aWLo + row * 48 + offB);
                    bl[1] = *(const uint32_t*)((const char*)aWLo + row * 48 + offB + 16);
                    #pragma unroll
                    for (int mi = 0; mi < 2; ++mi) {
                        mma16816(eacc[mi][nj], fAh[mi], bh);
                        mma16816(eacc[mi][nj], fAh[mi], bl);
                        mma16816(eacc[mi][nj], fAl[mi], bh);
                    }
                }
                #pragma unroll
                for (int mi = 0; mi < 2; ++mi)
                    #pragma unroll
                    for (int nj = 0; nj < 4; ++nj)
                        #pragma unroll
                        for (int q = 0; q < 4; ++q) acc[mi][h * 4 + nj][q] *= eacc[mi][nj][q];
            }
        }
        // ---- beta: eacc = zb @ bW^T (bf16x3), acc += eacc ----
        {
            uint32_t fAh[2][4], fAl[2][4];
            #pragma unroll
            for (int mi = 0; mi < 2; ++mi) {
                const int row = rA + mi * 16;
                ldmat4(fAh[mi], sb + 12288 + row * 48 + segOff);
                ldmat4(fAl[mi], sb + 18432 + row * 48 + segOff);
            }
            #pragma unroll
            for (int h = 0; h < 2; ++h) {
                float eacc[2][4][4];
                #pragma unroll
                for (int mi = 0; mi < 2; ++mi)
                    #pragma unroll
                    for (int nj = 0; nj < 4; ++nj)
                        #pragma unroll
                        for (int q = 0; q < 4; ++q) eacc[mi][nj][q] = 0.f;
                #pragma unroll
                for (int nj = 0; nj < 4; ++nj) {
                    const int row = wn * 64 + (h * 4 + nj) * 8 + (lane >> 2);
                    uint32_t bh[2], bl[2];
                    bh[0] = *(const uint32_t*)((const char*)bWHi + row * 48 + offB);
                    bh[1] = *(const uint32_t*)((const char*)bWHi + row * 48 + offB + 16);
                    bl[0] = *(const uint32_t*)((const char*)bWLo + row * 48 + offB);
                    bl[1] = *(const uint32_t*)((const char*)bWLo + row * 48 + offB + 16);
                    #pragma unroll
                    for (int mi = 0; mi < 2; ++mi) {
                        mma16816(eacc[mi][nj], fAh[mi], bh);
                        mma16816(eacc[mi][nj], fAh[mi], bl);
                        mma16816(eacc[mi][nj], fAl[mi], bh);
                    }
                }
                #pragma unroll
                for (int mi = 0; mi < 2; ++mi)
                    #pragma unroll
                    for (int nj = 0; nj < 4; ++nj)
                        #pragma unroll
                        for (int q = 0; q < 4; ++q) acc[mi][h * 4 + nj][q] += eacc[mi][nj][q];
            }
        }

        #pragma unroll
        for (int mi = 0; mi < 2; ++mi) {
            const int row = m0 + wm * 32 + mi * 16 + (lane >> 2);
            #pragma unroll
            for (int ni = 0; ni < 8; ++ni) {
                const int cl = wn * 64 + ni * 8 + (lane & 3) * 2;
                const float b0 = biasS[cl], b1 = biasS[cl + 1];
                *(float2*)(C + (size_t)row * ldc + n0 + cl)       = make_float2(acc[mi][ni][0] + b0, acc[mi][ni][1] + b1);
                *(float2*)(C + (size_t)(row + 8) * ldc + n0 + cl) = make_float2(acc[mi][ni][2] + b0, acc[mi][ni][3] + b1);
            }
        }
    } else {
        #pragma unroll
        for (int mi = 0; mi < 2; ++mi) {
            const int row = m0 + wm * 32 + mi * 16 + (lane >> 2);
            #pragma unroll
            for (int ni = 0; ni < 8; ++ni) {
                const int cl = wn * 64 + ni * 8 + (lane & 3) * 2;
                *(float2*)(C + (size_t)row * ldc + n0 + cl)       = make_float2(acc[mi][ni][0], acc[mi][ni][1]);
                *(float2*)(C + (size_t)(row + 8) * ldc + n0 + cl) = make_float2(acc[mi][ni][2], acc[mi][ni][3]);
            }
        }
    }
}

// ---------------- fused adapter pointwise + zwzb ----------------
__device__ __forceinline__ float sigf(float x) { return 1.f / (1.f + expf(-x)); }

__global__ __launch_bounds__(256)
void adapter_fused(const float* __restrict__ igpre, const float* __restrict__ hgpre,
                   const float* __restrict__ total_c,
                   const float* __restrict__ a_ln_i_w, const float* __restrict__ a_ln_i_b,
                   const float* __restrict__ a_ln_h_w, const float* __restrict__ a_ln_h_b,
                   const float* __restrict__ a_ln_c_w, const float* __restrict__ a_ln_c_b,
                   const float* __restrict__ nwT, const float* __restrict__ norm_zw_b,
                   __nv_bfloat16* __restrict__ zwzbHi, __nv_bfloat16* __restrict__ zwzbLo,
                   float* __restrict__ out, int writeFull)
{
    __shared__ float sada[8][128];
    const int w = threadIdx.x >> 5, lane = threadIdx.x & 31;
    const int b = blockIdx.x * 8 + w;

    float ig[4][4], hg[4][4];
    float s1i = 0.f, s2i = 0.f, s1h = 0.f, s2h = 0.f;
    #pragma unroll
    for (int k = 0; k < 4; ++k) {
        float4 v = *(const float4*)(igpre + (size_t)b * 512 + k * 128 + lane * 4);
        ig[k][0] = v.x; ig[k][1] = v.y; ig[k][2] = v.z; ig[k][3] = v.w;
        s1i += v.x + v.y + v.z + v.w;
        s2i += v.x * v.x + v.y * v.y + v.z * v.z + v.w * v.w;
        float4 u = *(const float4*)(hgpre + (size_t)b * 512 + k * 128 + lane * 4);
        hg[k][0] = u.x; hg[k][1] = u.y; hg[k][2] = u.z; hg[k][3] = u.w;
        s1h += u.x + u.y + u.z + u.w;
        s2h += u.x * u.x + u.y * u.y + u.z * u.z + u.w * u.w;
    }
    #pragma unroll
    for (int o = 16; o > 0; o >>= 1) {
        s1i += __shfl_xor_sync(0xffffffffu, s1i, o);
        s2i += __shfl_xor_sync(0xffffffffu, s2i, o);
        s1h += __shfl_xor_sync(0xffffffffu, s1h, o);
        s2h += __shfl_xor_sync(0xffffffffu, s2h, o);
    }
    const float muI = s1i * (1.f / 512.f);
    const float rsI = rsqrtf(s2i * (1.f / 512.f) - muI * muI + LN_EPS);
    const float muH = s1h * (1.f / 512.f);
    const float rsH = rsqrtf(s2h * (1.f / 512.f) - muH * muH + LN_EPS);

    float g[4][4];
    #pragma unroll
    for (int k = 0; k < 4; ++k) {
        float4 liw = *(const float4*)(a_ln_i_w + k * 128 + lane * 4);
        float4 lib = *(const float4*)(a_ln_i_b + k * 128 + lane * 4);
        float4 lhw = *(const float4*)(a_ln_h_w + k * 128 + lane * 4);
        float4 lhb = *(const float4*)(a_ln_h_b + k * 128 + lane * 4);
        const float* pw = &liw.x; const float* pb = &lib.x;
        const float* qw = &lhw.x; const float* qb = &lhb.x;
        #pragma unroll
        for (int q = 0; q < 4; ++q)
            g[k][q] = (ig[k][q] - muI) * rsI * pw[q] + pb[q]
                    + (hg[k][q] - muH) * rsH * qw[q] + qb[q];
    }

    float4 ac4 = *(const float4*)(total_c + (size_t)b * THW + 1024 + lane * 4);
    const float* acp = &ac4.x;
    float cpre[4];
    float sc = 0.f, sc2 = 0.f;
    #pragma unroll
    for (int q = 0; q < 4; ++q) {
        cpre[q] = sigf(g[1][q]) * acp[q] + sigf(g[0][q]) * tanhf(g[2][q]);
        sc += cpre[q]; sc2 += cpre[q] * cpre[q];
    }
    #pragma unroll
    for (int o = 16; o > 0; o >>= 1) {
        sc  += __shfl_xor_sync(0xffffffffu, sc, o);
        sc2 += __shfl_xor_sync(0xffffffffu, sc2, o);
    }
    const float mc = sc * (1.f / 128.f);
    const float rc = rsqrtf(sc2 * (1.f / 128.f) - mc * mc + LN_EPS);

    float4 lcw = *(const float4*)(a_ln_c_w + lane * 4);
    float4 lcb = *(const float4*)(a_ln_c_b + lane * 4);
    const float* cw = &lcw.x; const float* cb = &lcb.x;
    float acy[4], ada[4];
    #pragma unroll
    for (int q = 0; q < 4; ++q) {
        acy[q] = (cpre[q] - mc) * rc * cw[q] + cb[q];
        ada[q] = sigf(g[3][q]) * tanhf(acy[q]);
        sada[w][lane * 4 + q] = ada[q];
    }
    if (writeFull) {
        *(float4*)(out + OFF_H + (size_t)b * THW + 1024 + lane * 4) = make_float4(ada[0], ada[1], ada[2], ada[3]);
        *(float4*)(out + OFF_C + (size_t)b * THW + 1024 + lane * 4) = make_float4(acy[0], acy[1], acy[2], acy[3]);
    }
    __syncthreads();

    // zwzb: [zw|zb][b0+r][j] = sum_a sada[r][a] * nwT[a][j]  (+ norm_zw_b for j<128)
    const int j = threadIdx.x;
    float acc[8];
    #pragma unroll
    for (int r = 0; r < 8; ++r) acc[r] = 0.f;
    for (int a = 0; a < 128; ++a) {
        const float wv = __ldg(nwT + a * 256 + j);
        #pragma unroll
        for (int r = 0; r < 8; ++r) acc[r] += sada[r][a] * wv;
    }
    const float zbias = (j < 128) ? norm_zw_b[j] : 0.f;
    const int b0 = blockIdx.x * 8;
    #pragma unroll
    for (int r = 0; r < 8; ++r) {
        float v = acc[r] + zbias;
        __nv_bfloat16 h = __float2bfloat16(v);
        zwzbHi[(size_t)(b0 + r) * 256 + j] = h;
        zwzbLo[(size_t)(b0 + r) * 256 + j] = __float2bfloat16(v - __bfloat162float(h));
    }
}

// ---------------- main pointwise v2: 512 thr, fused stats ----------------
__device__ __forceinline__ void blockReduce4(float* v, int n, float* red, int t) {
    #pragma unroll
    for (int o = 16; o > 0; o >>= 1)
        for (int k = 0; k < 4; ++k) if (k < n) v[k] += __shfl_xor_sync(0xffffffffu, v[k], o);
    if ((t & 31) == 0)
        for (int k = 0; k < n; ++k) red[(t >> 5) * n + k] = v[k];
    __syncthreads();
    for (int k = 0; k < n; ++k) {
        float s = 0.f;
        for (int w = 0; w < 16; ++w) s += red[w * n + k];
        v[k] = s;
    }
    __syncthreads();
}

__global__ __launch_bounds__(512)
void main_pointwise(const float* __restrict__ ing, const float* __restrict__ hidg,
                    const float* __restrict__ total_c,
                    const float* __restrict__ ln_i_w, const float* __restrict__ ln_i_b,
                    const float* __restrict__ ln_h_w, const float* __restrict__ ln_h_b,
                    const float* __restrict__ ln_c_w, const float* __restrict__ ln_c_b,
                    float* __restrict__ out, int writeFull)
{
    __shared__ float sIn[4096];
    __shared__ float sHid[4096];
    __shared__ float red[64];
    const int b = blockIdx.x;
    const int t = threadIdx.x;

    const float4* pi = (const float4*)(ing  + (size_t)b * 4096);
    const float4* ph = (const float4*)(hidg + (size_t)b * 4096);
    float sums[4] = {0.f, 0.f, 0.f, 0.f};
    for (int i = t; i < 1024; i += 512) {
        float4 v = pi[i]; ((float4*)sIn)[i] = v;
        sums[0] += v.x + v.y + v.z + v.w;
        sums[1] += v.x * v.x + v.y * v.y + v.z * v.z + v.w * v.w;
        float4 u = ph[i]; ((float4*)sHid)[i] = u;
        sums[2] += u.x + u.y + u.z + u.w;
        sums[3] += u.x * u.x + u.y * u.y + u.z * u.z + u.w * u.w;
    }
    __syncthreads();
    blockReduce4(sums, 4, red, t);
    const float muI = sums[0] * (1.f / 4096.f);
    const float rsI = rsqrtf(sums[1] * (1.f / 4096.f) - muI * muI + LN_EPS);
    const float muH = sums[2] * (1.f / 4096.f);
    const float rsH = rsqrtf(sums[3] * (1.f / 4096.f) - muH * muH + LN_EPS);

    for (int i = t; i < 1024; i += 512) {
        float4 vi = ((float4*)sIn)[i];
        float4 vh = ((float4*)sHid)[i];
        float4 liw = ((const float4*)ln_i_w)[i];
        float4 lib = ((const float4*)ln_i_b)[i];
        float4 lhw = ((const float4*)ln_h_w)[i];
        float4 lhb = ((const float4*)ln_h_b)[i];
        float4 g;
        g.x = (vi.x - muI) * rsI * liw.x + lib.x + (vh.x - muH) * rsH * lhw.x + lhb.x;
        g.y = (vi.y - muI) * rsI * liw.y + lib.y + (vh.y - muH) * rsH * lhw.y + lhb.y;
        g.z = (vi.z - muI) * rsI * liw.z + lib.z + (vh.z - muH) * rsH * lhw.z + lhb.z;
        g.w = (vi.w - muI) * rsI * liw.w + lib.w + (vh.w - muH) * rsH * lhw.w + lhb.w;
        ((float4*)sIn)[i] = g;
    }
    __syncthreads();

    float cp[2], gov[2];
    float csum[4] = {0.f, 0.f, 0.f, 0.f};
    #pragma unroll
    for (int k = 0; k < 2; ++k) {
        const int h = t + k * 512;
        float gi = sIn[h], gj = sIn[1024 + h], gf = sIn[2048 + h], go = sIn[3072 + h];
        float cx = total_c[(size_t)b * THW + h];
        float c = sigf(gf) * cx + sigf(gi) * tanhf(gj);
        cp[k] = c; gov[k] = go;
        csum[0] += c; csum[1] += c * c;
    }
    blockReduce4(csum, 2, red, t);
    const float mc = csum[0] * (1.f / 1024.f);
    const float rc = rsqrtf(csum[1] * (1.f / 1024.f) - mc * mc + LN_EPS);

    #pragma unroll
    for (int k = 0; k < 2; ++k) {
        const int h = t + k * 512;
        float cy = (cp[k] - mc) * rc * ln_c_w[h] + ln_c_b[h];
        float hy = sigf(gov[k]) * tanhf(cy);
        out[(size_t)b * 1024 + h] = hy;
        if (writeFull) {
            out[OFF_H + (size_t)b * THW + h] = hy;
            out[OFF_C + (size_t)b * THW + h] = cy;
        }
    }
}

// ---------------- launch ----------------
extern "C" void kernel_launch(void* const* d_in, const int* in_sizes, int n_in,
                              void* d_out, int out_size)
{
    const float* x           = (const float*)d_in[0];
    const float* total_h     = (const float*)d_in[1];
    const float* total_c     = (const float*)d_in[2];
    const float* w_ih        = (const float*)d_in[3];
    const float* w_hh        = (const float*)d_in[4];
    const float* b_ih        = (const float*)d_in[5];
    const float* b_hh        = (const float*)d_in[6];
    const float* ln_i_w      = (const float*)d_in[7];
    const float* ln_i_b      = (const float*)d_in[8];
    const float* ln_h_w      = (const float*)d_in[9];
    const float* ln_h_b      = (const float*)d_in[10];
    const float* ln_c_w      = (const float*)d_in[11];
    const float* ln_c_b      = (const float*)d_in[12];
    const float* norm_zw_w   = (const float*)d_in[13];
    const float* norm_zw_b   = (const float*)d_in[14];
    const float* norm_alpha_w= (const float*)d_in[15];
    const float* bias_zb_w   = (const float*)d_in[16];
    const float* bias_beta_w = (const float*)d_in[17];
    const float* a_w_ih      = (const float*)d_in[18];
    const float* a_w_hh      = (const float*)d_in[19];
    const float* a_ln_i_w    = (const float*)d_in[20];
    const float* a_ln_i_b    = (const float*)d_in[21];
    const float* a_ln_h_w    = (const float*)d_in[22];
    const float* a_ln_h_b    = (const float*)d_in[23];
    const float* a_ln_c_w    = (const float*)d_in[24];
    const float* a_ln_c_b    = (const float*)d_in[25];
    float* out = (float*)d_out;

    const int writeFull = (size_t)out_size >= OUT_FULL_SIZE ? 1 : 0;

    __nv_bfloat16 *xh_hi, *xh_lo, *wm_hi, *wm_lo, *awih_hi, *awih_lo, *ah_hi, *ah_lo, *awhh_hi, *awhh_lo;
    __nv_bfloat16 *zwzbHi, *zwzbLo, *aWHi, *aWLo, *bWHi, *bWLo;
    float *igpre, *hgpre, *gates, *nwT;
    cudaGetSymbolAddress((void**)&xh_hi, g_xh_hi);     cudaGetSymbolAddress((void**)&xh_lo, g_xh_lo);
    cudaGetSymbolAddress((void**)&wm_hi, g_wm_hi);     cudaGetSymbolAddress((void**)&wm_lo, g_wm_lo);
    cudaGetSymbolAddress((void**)&awih_hi, g_awih_hi); cudaGetSymbolAddress((void**)&awih_lo, g_awih_lo);
    cudaGetSymbolAddress((void**)&ah_hi, g_ah_hi);     cudaGetSymbolAddress((void**)&ah_lo, g_ah_lo);
    cudaGetSymbolAddress((void**)&awhh_hi, g_awhh_hi); cudaGetSymbolAddress((void**)&awhh_lo, g_awhh_lo);
    cudaGetSymbolAddress((void**)&zwzbHi, g_zwzbHi);   cudaGetSymbolAddress((void**)&zwzbLo, g_zwzbLo);
    cudaGetSymbolAddress((void**)&aWHi, g_aWHi);       cudaGetSymbolAddress((void**)&aWLo, g_aWLo);
    cudaGetSymbolAddress((void**)&bWHi, g_bWHi);       cudaGetSymbolAddress((void**)&bWLo, g_bWLo);
    cudaGetSymbolAddress((void**)&nwT, g_nwT);
    cudaGetSymbolAddress((void**)&igpre, g_igpre);     cudaGetSymbolAddress((void**)&hgpre, g_hgpre);
    cudaGetSymbolAddress((void**)&gates, g_gates);

    cudaFuncSetAttribute(gemm_hmma<true, false>,  cudaFuncAttributeMaxDynamicSharedMemorySize, SMEM_SZ);
    cudaFuncSetAttribute(gemm_hmma<false, true>,  cudaFuncAttributeMaxDynamicSharedMemorySize, SMEM_SZ);

    // 0: all conversions
    split_all<<<9248, 256>>>(w_ih, w_hh, x, total_h, a_w_ih, a_w_hh,
                             norm_alpha_w, bias_beta_w, norm_zw_w, bias_zb_w,
                             wm_hi, wm_lo, xh_hi, xh_lo, ah_hi, ah_lo,
                             awih_hi, awih_lo, awhh_hi, awhh_lo,
                             aWHi, aWLo, bWHi, bWLo, nwT);

    // 1: adapter GEMMs (dual)
    gemm_hmma<false, true><<<dim3(2, 32, 2), 512, SMEM_SZ>>>(
        xh_hi, xh_lo, 2048, 0, awih_hi, awih_lo, 0,
        igpre, 512, 0, 2048,
        ah_hi, ah_lo, 128, awhh_hi, awhh_lo, hgpre, 512, 128,
        nullptr, nullptr, nullptr, nullptr, nullptr, nullptr, nullptr, nullptr);

    // 2: adapter pointwise + zwzb fused
    adapter_fused<<<Bsz / 8, 256>>>(
        igpre, hgpre, total_c,
        a_ln_i_w, a_ln_i_b, a_ln_h_w, a_ln_h_b, a_ln_c_w, a_ln_c_b,
        nwT, norm_zw_b, zwzbHi, zwzbLo, out, writeFull);

    // 3 (profiled): main GEMMs + fused alpha/beta epilogue
    gemm_hmma<true, false><<<dim3(16, 32, 2), 512, SMEM_SZ>>>(
        xh_hi, xh_lo, 2048, 1024, wm_hi, wm_lo, (long)4096 * 1024,
        gates, 4096, (long)4096 * 4096, 1024,
        nullptr, nullptr, 0, nullptr, nullptr, nullptr, 0, 0,
        zwzbHi, zwzbLo, aWHi, aWLo, bWHi, bWLo, b_ih, b_hh);

    // 4: main pointwise
    main_pointwise<<<Bsz, 512>>>(
        gates, gates + (size_t)4096 * 4096, total_c,
        ln_i_w, ln_i_b, ln_h_w, ln_h_b, ln_c_w, ln_c_b,
        out, writeFull);
}